// round 2
// baseline (speedup 1.0000x reference)
#include <cuda_runtime.h>
#include <cstdint>
#include <cstddef>

// Problem constants
#define B_  16
#define U_  512
#define L_  1024
#define H_  8
#define D_  64
#define SCALE_ 0.125f   // 1/sqrt(64)

// Scratch (device globals — allocation-free rule). 16B aligned for float4.
__device__ __align__(256) float g_Q[(size_t)B_ * U_ * L_];
__device__ __align__(256) float g_K[(size_t)B_ * U_ * L_];
__device__ __align__(256) float g_C[(size_t)B_ * U_ * L_];

// ---------------------------------------------------------------------------
// Channel-mix GEMM: Out[b][o][l] = sum_u W[o][u] * X[b][u][l]
// If FUSE: X = 0.5*(X1 + X2)  (used for E = 0.5*(Q + C))
// Block tile 128(M) x 128(N), k-tile 8, 256 threads, 8x8 micro-tile.
// ---------------------------------------------------------------------------
template <bool FUSE>
__global__ __launch_bounds__(256, 2) void mix_gemm(
    const float* __restrict__ W,
    const float* __restrict__ X1,
    const float* __restrict__ X2,
    float* __restrict__ Out)
{
    __shared__ float As[8][132];   // [ku][oi], padded: conflict-free transpose store
    __shared__ float Bs[8][128];   // [ku][li]

    const int b    = blockIdx.z;
    const int row0 = blockIdx.y * 128;
    const int col0 = blockIdx.x * 128;
    const int tid  = threadIdx.x;
    const int to   = tid >> 4;     // 0..15 (output row group)
    const int tl   = tid & 15;     // 0..15 (output col group)

    // staging thread mapping
    const int a_o  = tid >> 1;           // 0..127
    const int a_u4 = (tid & 1) * 4;      // 0 or 4
    const int b_ku = tid >> 5;           // 0..7
    const int b_l4 = (tid & 31) * 4;     // 0..124

    const float* Wp  = W  + (size_t)(row0 + a_o) * U_ + a_u4;
    const float* X1p = X1 + ((size_t)b * U_ + b_ku) * L_ + col0 + b_l4;
    const float* X2p = FUSE ? (X2 + ((size_t)b * U_ + b_ku) * L_ + col0 + b_l4) : nullptr;

    float acc[2][2][4][4];
#pragma unroll
    for (int io = 0; io < 2; io++)
#pragma unroll
        for (int il = 0; il < 2; il++)
#pragma unroll
            for (int i = 0; i < 4; i++)
#pragma unroll
                for (int j = 0; j < 4; j++) acc[io][il][i][j] = 0.f;

    // prefetch k-tile 0 into registers
    float4 aR = *(const float4*)Wp;
    float4 bR;
    {
        float4 p = *(const float4*)X1p;
        if (FUSE) {
            float4 q = *(const float4*)X2p;
            bR = make_float4(0.5f * (p.x + q.x), 0.5f * (p.y + q.y),
                             0.5f * (p.z + q.z), 0.5f * (p.w + q.w));
        } else {
            bR = p;
        }
    }

    const int NT = U_ / 8;  // 64 k-tiles
    for (int kt = 0; kt < NT; kt++) {
        // stage (smem guaranteed free by bottom sync of previous iter)
        As[a_u4 + 0][a_o] = aR.x;
        As[a_u4 + 1][a_o] = aR.y;
        As[a_u4 + 2][a_o] = aR.z;
        As[a_u4 + 3][a_o] = aR.w;
        *(float4*)&Bs[b_ku][b_l4] = bR;
        __syncthreads();

        // prefetch next tile from global while computing this one
        if (kt + 1 < NT) {
            aR = *(const float4*)(Wp + (size_t)(kt + 1) * 8);
            float4 p = *(const float4*)(X1p + (size_t)(kt + 1) * 8 * L_);
            if (FUSE) {
                float4 q = *(const float4*)(X2p + (size_t)(kt + 1) * 8 * L_);
                bR = make_float4(0.5f * (p.x + q.x), 0.5f * (p.y + q.y),
                                 0.5f * (p.z + q.z), 0.5f * (p.w + q.w));
            } else {
                bR = p;
            }
        }

#pragma unroll
        for (int ku = 0; ku < 8; ku++) {
            float4 a0 = *(const float4*)&As[ku][to * 4];
            float4 a1 = *(const float4*)&As[ku][to * 4 + 64];
            float4 b0 = *(const float4*)&Bs[ku][tl * 4];
            float4 b1 = *(const float4*)&Bs[ku][tl * 4 + 64];
            float av[2][4] = {{a0.x, a0.y, a0.z, a0.w}, {a1.x, a1.y, a1.z, a1.w}};
            float bv[2][4] = {{b0.x, b0.y, b0.z, b0.w}, {b1.x, b1.y, b1.z, b1.w}};
#pragma unroll
            for (int io = 0; io < 2; io++)
#pragma unroll
                for (int i = 0; i < 4; i++)
#pragma unroll
                    for (int il = 0; il < 2; il++)
#pragma unroll
                        for (int j = 0; j < 4; j++)
                            acc[io][il][i][j] = fmaf(av[io][i], bv[il][j], acc[io][il][i][j]);
        }
        __syncthreads();
    }

    // write 128-aligned float4s
#pragma unroll
    for (int io = 0; io < 2; io++)
#pragma unroll
        for (int i = 0; i < 4; i++) {
            const int row = row0 + io * 64 + to * 4 + i;
            float* op = Out + ((size_t)b * U_ + row) * L_ + col0;
#pragma unroll
            for (int il = 0; il < 2; il++) {
                float4 v = make_float4(acc[io][il][i][0], acc[io][il][i][1],
                                       acc[io][il][i][2], acc[io][il][i][3]);
                *(float4*)(op + il * 64 + tl * 4) = v;
            }
        }
}

// ---------------------------------------------------------------------------
// Fused masked ReLU attention:
//   per (b, h, 128 x-rows): loop y in 64-tiles:
//     S = relu( (scale*Qh)^T Kh ) * mask     (TX=128 x TY=64, in registers)
//     C += Kh * S^T                          (d=64 x TX=128, register-resident)
//     cnt[x] += row-sum(mask)
//   C[:, x] *= 1/max(cnt[x],1); write to g_C
//
// NOTE: mask arrives as int32 (harness converts jax bool -> int32). We pack
// each int32 (0/1) down to one byte during smem staging.
// ---------------------------------------------------------------------------

// smem layout (float offsets)
#define QS_OFF   0                    // [64][128]  Q^T tile (scaled)
#define KS_OFF   8192                 // [64][64]   K tile [kd][yj]
#define KST_OFF  12288                // [64][68]   K transposed [yj][kd]
#define SST_OFF  16640                // [64][132]  S transposed [yj][xi]
#define MS_BYTE  100352               // (16640+8448)*4 : mask tile bytes
#define MS_STRIDE 68                  // padded byte row stride (bank-conflict-free)
#define CNT_OFF  27264                // int cnt[128]
#define ATTN_SMEM_BYTES ((size_t)(27264 + 128) * 4)   // 109568 B

__global__ __launch_bounds__(256, 2) void attn_kernel(
    const float* __restrict__ Q, const float* __restrict__ K,
    const int* __restrict__ mask, float* __restrict__ C)
{
    extern __shared__ float sm[];
    float* Qs  = sm + QS_OFF;
    float* Ks  = sm + KS_OFF;
    float* Kst = sm + KST_OFF;
    float* Sst = sm + SST_OFF;
    uint8_t* Ms = (uint8_t*)sm + MS_BYTE;
    int* cnts = (int*)(sm + CNT_OFF);

    const int b  = blockIdx.z;
    const int h  = blockIdx.x;          // h fastest-varying: mask tile L2 reuse
    const int x0 = blockIdx.y * 128;
    const int tid = threadIdx.x;
    const int tx = tid & 15;   // x group
    const int ty = tid >> 4;   // y group (S) / kd group (C)

    if (tid < 128) cnts[tid] = 0;

    // Load Q tile (64 x 128), scale folded in
    const float* Qbase = Q + ((size_t)(b * U_ + h * D_)) * L_ + x0;
#pragma unroll
    for (int r = 0; r < 8; r++) {
        int idx = tid + r * 256;
        int kd = idx >> 5;
        int x4 = (idx & 31) << 2;
        float4 v = *(const float4*)(Qbase + (size_t)kd * L_ + x4);
        v.x *= SCALE_; v.y *= SCALE_; v.z *= SCALE_; v.w *= SCALE_;
        *(float4*)&Qs[kd * 128 + x4] = v;
    }

    float cc[4][2][4];
#pragma unroll
    for (int a = 0; a < 4; a++)
#pragma unroll
        for (int hx = 0; hx < 2; hx++)
#pragma unroll
            for (int j = 0; j < 4; j++) cc[a][hx][j] = 0.f;

    int cnt[2][4];
#pragma unroll
    for (int hx = 0; hx < 2; hx++)
#pragma unroll
        for (int i = 0; i < 4; i++) cnt[hx][i] = 0;

    const float* Kbase = K + ((size_t)(b * U_ + h * D_)) * L_;
    const int*   Mbase = mask + ((size_t)b * L_ + x0) * L_;

    const int xs = tx * 4;
    const int ys = ty * 4;

    for (int yt = 0; yt < L_ / 64; yt++) {
        const int y0 = yt * 64;
        __syncthreads();   // previous C-GEMM done reading Ks/Kst/Sst; Qs ready (iter 0)

        // Load K tile -> Ks and transposed Kst
#pragma unroll
        for (int r = 0; r < 4; r++) {
            int idx = tid + r * 256;
            int kd = idx >> 4;
            int y4 = (idx & 15) << 2;
            float4 v = *(const float4*)(Kbase + (size_t)kd * L_ + y0 + y4);
            *(float4*)&Ks[kd * 64 + y4] = v;
            Kst[(y4 + 0) * 68 + kd] = v.x;
            Kst[(y4 + 1) * 68 + kd] = v.y;
            Kst[(y4 + 2) * 68 + kd] = v.z;
            Kst[(y4 + 3) * 68 + kd] = v.w;
        }
        // Load mask tile (128 rows x 64 int32), pack to bytes in smem
#pragma unroll
        for (int r = 0; r < 8; r++) {
            int idx = tid + r * 256;
            int xr = idx >> 4;
            int yw = idx & 15;
            int4 m = *(const int4*)(Mbase + (size_t)xr * L_ + y0 + yw * 4);
            uint32_t packed = (m.x != 0 ? 1u : 0u)
                            | (m.y != 0 ? 1u << 8 : 0u)
                            | (m.z != 0 ? 1u << 16 : 0u)
                            | (m.w != 0 ? 1u << 24 : 0u);
            *(uint32_t*)(Ms + xr * MS_STRIDE + yw * 4) = packed;
        }
        __syncthreads();

        // S = Q^T K  (per-thread 8x x 4y)
        float s[2][4][4];
#pragma unroll
        for (int hx = 0; hx < 2; hx++)
#pragma unroll
            for (int i = 0; i < 4; i++)
#pragma unroll
                for (int j = 0; j < 4; j++) s[hx][i][j] = 0.f;

#pragma unroll 4
        for (int kd = 0; kd < 64; kd++) {
            float4 q0 = *(const float4*)&Qs[kd * 128 + xs];
            float4 q1 = *(const float4*)&Qs[kd * 128 + xs + 64];
            float4 kv = *(const float4*)&Ks[kd * 64 + ys];
            float qa[2][4] = {{q0.x, q0.y, q0.z, q0.w}, {q1.x, q1.y, q1.z, q1.w}};
            float kb[4] = {kv.x, kv.y, kv.z, kv.w};
#pragma unroll
            for (int hx = 0; hx < 2; hx++)
#pragma unroll
                for (int i = 0; i < 4; i++)
#pragma unroll
                    for (int j = 0; j < 4; j++)
                        s[hx][i][j] = fmaf(qa[hx][i], kb[j], s[hx][i][j]);
        }

        // relu + mask + per-row counts
#pragma unroll
        for (int hx = 0; hx < 2; hx++)
#pragma unroll
            for (int i = 0; i < 4; i++) {
                int xr = xs + hx * 64 + i;
                uint32_t mw = *(const uint32_t*)(Ms + xr * MS_STRIDE + ys);
#pragma unroll
                for (int j = 0; j < 4; j++) {
                    uint32_t mb = (mw >> (8 * j)) & 0xFFu;
                    float v = s[hx][i][j];
                    v = v > 0.f ? v : 0.f;
                    v = mb ? v : 0.f;
                    s[hx][i][j] = v;
                    cnt[hx][i] += mb ? 1 : 0;
                }
            }

        // stage S transposed for the C-GEMM
#pragma unroll
        for (int j = 0; j < 4; j++)
#pragma unroll
            for (int hx = 0; hx < 2; hx++) {
                float4 v = make_float4(s[hx][0][j], s[hx][1][j], s[hx][2][j], s[hx][3][j]);
                *(float4*)&Sst[(ys + j) * 132 + xs + hx * 64] = v;
            }
        __syncthreads();

        // C[kd][xi] += sum_yj Kst[yj][kd] * Sst[yj][xi]   (per-thread 4kd x 8xi)
#pragma unroll 4
        for (int yj = 0; yj < 64; yj++) {
            float4 kv = *(const float4*)&Kst[yj * 68 + ty * 4];
            float4 s0 = *(const float4*)&Sst[yj * 132 + tx * 4];
            float4 s1 = *(const float4*)&Sst[yj * 132 + tx * 4 + 64];
            float ka[4] = {kv.x, kv.y, kv.z, kv.w};
            float sb[2][4] = {{s0.x, s0.y, s0.z, s0.w}, {s1.x, s1.y, s1.z, s1.w}};
#pragma unroll
            for (int a = 0; a < 4; a++)
#pragma unroll
                for (int hx = 0; hx < 2; hx++)
#pragma unroll
                    for (int j = 0; j < 4; j++)
                        cc[a][hx][j] = fmaf(ka[a], sb[hx][j], cc[a][hx][j]);
        }
    }

    // reduce per-row mask counts across the 16 y-group threads
#pragma unroll
    for (int hx = 0; hx < 2; hx++)
#pragma unroll
        for (int i = 0; i < 4; i++)
            atomicAdd(&cnts[xs + hx * 64 + i], cnt[hx][i]);
    __syncthreads();

    float inv[2][4];
#pragma unroll
    for (int hx = 0; hx < 2; hx++)
#pragma unroll
        for (int j = 0; j < 4; j++) {
            int c = cnts[xs + hx * 64 + j];
            inv[hx][j] = 1.0f / (float)(c > 0 ? c : 1);
        }

    float* Cbase = C + ((size_t)(b * U_ + h * D_ + ty * 4)) * L_ + x0;
#pragma unroll
    for (int a = 0; a < 4; a++)
#pragma unroll
        for (int hx = 0; hx < 2; hx++) {
            float4 v = make_float4(cc[a][hx][0] * inv[hx][0], cc[a][hx][1] * inv[hx][1],
                                   cc[a][hx][2] * inv[hx][2], cc[a][hx][3] * inv[hx][3]);
            *(float4*)(Cbase + (size_t)a * L_ + hx * 64 + tx * 4) = v;
        }
}

// ---------------------------------------------------------------------------
extern "C" void kernel_launch(void* const* d_in, const int* in_sizes, int n_in,
                              void* d_out, int out_size)
{
    const float* x  = (const float*)d_in[0];
    const float* y  = (const float*)d_in[1];
    const int*   mk = (const int*)d_in[2];
    const float* wq = (const float*)d_in[3];
    const float* wk = (const float*)d_in[4];
    const float* wo = (const float*)d_in[5];
    float* out = (float*)d_out;

    float *Qp, *Kp, *Cp;
    cudaGetSymbolAddress((void**)&Qp, g_Q);
    cudaGetSymbolAddress((void**)&Kp, g_K);
    cudaGetSymbolAddress((void**)&Cp, g_C);

    cudaFuncSetAttribute(attn_kernel, cudaFuncAttributeMaxDynamicSharedMemorySize,
                         (int)ATTN_SMEM_BYTES);

    dim3 gg(L_ / 128, U_ / 128, B_);   // (8, 4, 16)
    mix_gemm<false><<<gg, 256>>>(wq, x, nullptr, Qp);
    mix_gemm<false><<<gg, 256>>>(wk, y, nullptr, Kp);
    attn_kernel<<<dim3(H_, L_ / 128, B_), 256, ATTN_SMEM_BYTES>>>(Qp, Kp, mk, Cp);
    mix_gemm<true><<<gg, 256>>>(wo, Qp, Cp, out);
}

// round 8
// speedup vs baseline: 1.3156x; 1.3156x over previous
#include <cuda_runtime.h>
#include <cuda_bf16.h>
#include <cstdint>
#include <cstddef>

// Problem constants
#define B_  16
#define U_  512
#define L_  1024
#define H_  8
#define D_  64
#define SCALE_ 0.125f   // 1/sqrt(64)

// Scratch (device globals — allocation-free rule).
__device__ __align__(256) float g_Q[(size_t)B_ * U_ * L_];
__device__ __align__(256) float g_K[(size_t)B_ * U_ * L_];
__device__ __align__(256) float g_C[(size_t)B_ * U_ * L_];

// ===========================================================================
// Arch gating: tcgen05 is arch-specific; the harness also builds a non-'a'
// target where these instructions are illegal. Stub the whole GEMM body there.
// ===========================================================================
#if defined(__CUDA_ARCH_FEAT_SM103_ALL) || defined(__CUDA_ARCH_FEAT_SM100_ALL) || \
    defined(__CUDA_ARCH_FAMILY_SPECIFIC__) || defined(__CUDA_ARCH_SPECIFIC__)
#define TC_OK 1
#else
#define TC_OK 0
#endif

__device__ __forceinline__ uint32_t smem_to_u32(const void* p) {
    uint32_t a;
    asm("{ .reg .u64 t; cvta.to.shared.u64 t, %1; cvt.u32.u64 %0, t; }" : "=r"(a) : "l"(p));
    return a;
}
#define MBARRIER_INIT(mbar, count) \
    asm volatile("mbarrier.init.shared.b64 [%0], %1;" \
                 :: "r"((uint32_t)(mbar)), "r"((uint32_t)(count)) : "memory")
#define MBARRIER_WAIT_PARITY(mbar, parity) do {                                   \
    uint32_t _m = (uint32_t)(mbar); uint32_t _p = (uint32_t)(parity);             \
    asm volatile("{\n\t.reg .pred P1;\n\t"                                        \
        "WAIT_LOOP_%=:\n\t"                                                        \
        "mbarrier.try_wait.parity.acquire.cta.shared::cta.b64 P1, [%0], %1, 0x989680;\n\t" \
        "@P1 bra.uni WAIT_DONE_%=;\n\t"                                            \
        "bra.uni WAIT_LOOP_%=;\n\t"                                                \
        "WAIT_DONE_%=:\n\t}" :: "r"(_m), "r"(_p) : "memory");                      \
} while (0)
#define FENCE_PROXY_ASYNC_SHARED_CTA() asm volatile("fence.proxy.async.shared::cta;" ::: "memory")

#if TC_OK
__device__ __forceinline__ uint32_t elect_one_pred() {
    uint32_t pred;
    asm volatile("{\n\t.reg .pred p;\n\telect.sync _|p, 0xFFFFFFFF;\n\tselp.b32 %0, 1, 0, p;\n\t}"
                 : "=r"(pred));
    return pred;
}
#define TCGEN05_ALLOC(smem_result_addr, nCols) \
    asm volatile("tcgen05.alloc.cta_group::1.sync.aligned.shared::cta.b32 [%0], %1;" \
                 :: "r"((uint32_t)(smem_result_addr)), "r"((uint32_t)(nCols)) : "memory")
#define TCGEN05_DEALLOC(tmem_addr, nCols) \
    asm volatile("tcgen05.dealloc.cta_group::1.sync.aligned.b32 %0, %1;" \
                 :: "r"(tmem_addr), "r"((uint32_t)(nCols)))
#define TCGEN05_COMMIT(mbar) \
    asm volatile("tcgen05.commit.cta_group::1.mbarrier::arrive::one.shared::cluster.b64 [%0];" \
                 :: "r"((uint32_t)(mbar)) : "memory")
#define TCGEN05_FENCE_BEFORE() asm volatile("tcgen05.fence::before_thread_sync;" ::: "memory")
#define TCGEN05_FENCE_AFTER()  asm volatile("tcgen05.fence::after_thread_sync;"  ::: "memory")
#define TCGEN05_WAIT_LD()      asm volatile("tcgen05.wait::ld.sync.aligned;"     ::: "memory")
#define TCGEN05_LD_32X32B_X32(r, tmem_addr) \
    asm volatile( \
        "tcgen05.ld.sync.aligned.32x32b.x32.b32 " \
        "{%0, %1, %2, %3, %4, %5, %6, %7, " \
        " %8, %9, %10, %11, %12, %13, %14, %15, " \
        " %16, %17, %18, %19, %20, %21, %22, %23, " \
        " %24, %25, %26, %27, %28, %29, %30, %31}, [%32];" \
        : "=r"((r)[0]),  "=r"((r)[1]),  "=r"((r)[2]),  "=r"((r)[3]), \
          "=r"((r)[4]),  "=r"((r)[5]),  "=r"((r)[6]),  "=r"((r)[7]), \
          "=r"((r)[8]),  "=r"((r)[9]),  "=r"((r)[10]), "=r"((r)[11]), \
          "=r"((r)[12]), "=r"((r)[13]), "=r"((r)[14]), "=r"((r)[15]), \
          "=r"((r)[16]), "=r"((r)[17]), "=r"((r)[18]), "=r"((r)[19]), \
          "=r"((r)[20]), "=r"((r)[21]), "=r"((r)[22]), "=r"((r)[23]), \
          "=r"((r)[24]), "=r"((r)[25]), "=r"((r)[26]), "=r"((r)[27]), \
          "=r"((r)[28]), "=r"((r)[29]), "=r"((r)[30]), "=r"((r)[31]) \
        : "r"(tmem_addr))

// SS-mode f16-kind MMA (bf16 operands via idesc), cta_group::1
__device__ __forceinline__ void mma_f16_ss(uint32_t d_tmem, uint64_t a_desc,
                                           uint64_t b_desc, uint32_t idesc,
                                           uint32_t enable) {
    asm volatile(
        "{\n\t"
        ".reg .pred p;\n\t"
        "setp.ne.u32 p, %5, 0;\n\t"
        "tcgen05.mma.cta_group::1.kind::f16 [%0], %1, %2, %3, {%4, %4, %4, %4}, p;\n\t"
        "}"
        :: "r"(d_tmem), "l"(a_desc), "l"(b_desc), "r"(idesc), "r"(0u), "r"(enable)
        : "memory");
}
#endif  // TC_OK

// K-major SW128 descriptor: LBO=1 (16B), SBO=64 (1024B), version=1, SW128=2
__device__ __forceinline__ uint64_t desc_k_major(uint32_t addr) {
    return ((uint64_t)(addr >> 4) & 0x3FFF)
         | (1ull << 16) | (64ull << 32) | (1ull << 46) | (2ull << 61);
}

#define SW128(off) ((off) ^ (((off) >> 3) & 0x70))

// idesc (validated field layout, test_mma's 0x8080490 with N widened to 128):
// dtype F32 (1<<4) | atype BF16 (1<<7) | btype BF16 (1<<10)
// | (N=128/8)<<17 | (M=128/16)<<24   = 0x8200490
#define IDESC_BF16 0x8200490u

// split: hi = rn-bf16(x), lo = rn-bf16(x - hi); error ~2^-18 per product
__device__ __forceinline__ void bf16_split(float x, uint16_t& hi, uint16_t& lo) {
    __nv_bfloat16 h = __float2bfloat16(x);
    float r = x - __bfloat162float(h);
    __nv_bfloat16 l = __float2bfloat16(r);
    hi = __bfloat16_as_ushort(h);
    lo = __bfloat16_as_ushort(l);
}

// ===========================================================================
// tcgen05 split-bf16 channel-mix GEMM — SERIALIZED bisection version:
//   Out[b][o][l] = sum_u W[o][u] * X[b][u][l],  optionally X = 0.5*(X1+X2)
//   M=128 x N=128, K=512 in 8 chunks of 64. ONE smem buffer; per chunk:
//   stage -> syncthreads -> elect-MMA(12) -> commit -> all-wait(mbar, c&1).
//   TMEM: alloc 512 cols (as in all validated MMA examples), D at col 0.
// ===========================================================================
#define TCG_SMEM_BYTES 66688   // 64KB buffer + align slack + ctrl

template <bool FUSE>
__global__ __launch_bounds__(256, 1) __cluster_dims__(1, 1, 1) void tc_gemm(
    const float* __restrict__ W,
    const float* __restrict__ X1,
    const float* __restrict__ X2,
    float* __restrict__ Out)
{
#if TC_OK
    extern __shared__ uint8_t dsm[];
    const uint32_t raw  = smem_to_u32(dsm);
    const uint32_t base = (raw + 1023u) & ~1023u;
    uint8_t* p = dsm + (base - raw);

    // buffer byte offsets: Ahi 0 | Alo 16384 | Bhi 32768 | Blo 49152
    const uint32_t ctrl = base + 65536;        // tmem ptr
    const uint32_t mbar = ctrl + 8;

    const int b    = blockIdx.z;
    const int row0 = blockIdx.y * 128;   // o
    const int col0 = blockIdx.x * 128;   // l
    const int tid  = threadIdx.x;
    const int wid  = tid >> 5;
    const int lid  = tid & 31;

    if (wid == 0) {
        TCGEN05_ALLOC(ctrl, 512);
    }
    if (tid == 0) MBARRIER_INIT(mbar, 1);
    __syncthreads();
    uint32_t tmem;
    asm volatile("ld.shared.b32 %0, [%1];" : "=r"(tmem) : "r"(ctrl));

    const float* Wb  = W + (size_t)row0 * U_;
    const float* X1b = X1 + (size_t)b * U_ * L_ + col0;
    const float* X2b = FUSE ? (X2 + (size_t)b * U_ * L_ + col0) : nullptr;

    const int NC = U_ / 64;   // 8 chunks
    for (int c = 0; c < NC; c++) {
        const int k0 = c * 64;
        // ---- stage A: W[128m x 64k] -> bf16 hi/lo, K-major SW128 ----
#pragma unroll
        for (int t = 0; t < 8; t++) {
            int idx = tid + t * 256;
            int m  = idx >> 4;            // 0..127
            int k4 = (idx & 15) << 2;     // 0..60
            float4 v = *(const float4*)(Wb + (size_t)m * U_ + k0 + k4);
            uint16_t h0, l0, h1, l1, h2, l2, h3, l3;
            bf16_split(v.x, h0, l0); bf16_split(v.y, h1, l1);
            bf16_split(v.z, h2, l2); bf16_split(v.w, h3, l3);
            uint2 hv = make_uint2((uint32_t)h0 | ((uint32_t)h1 << 16),
                                  (uint32_t)h2 | ((uint32_t)h3 << 16));
            uint2 lv = make_uint2((uint32_t)l0 | ((uint32_t)l1 << 16),
                                  (uint32_t)l2 | ((uint32_t)l3 << 16));
            uint32_t off = (uint32_t)((m >> 3) * 1024 + (m & 7) * 128 + k4 * 2);
            uint32_t sw = SW128(off);
            *(uint2*)(p + sw)         = hv;
            *(uint2*)(p + 16384 + sw) = lv;
        }
        // ---- stage B: X[64k x 128n] -> transposed bf16 [128n x 64k] hi/lo ----
        {
            float r[8][4];
#pragma unroll
            for (int kk = 0; kk < 8; kk++) {
                const float* xr = X1b + (size_t)(k0 + wid * 8 + kk) * L_;
                const float* yr = FUSE ? (X2b + (size_t)(k0 + wid * 8 + kk) * L_) : nullptr;
#pragma unroll
                for (int ei = 0; ei < 4; ei++) {
                    int n = lid + 32 * ei;
                    float v = xr[n];
                    if (FUSE) v = 0.5f * (v + yr[n]);
                    r[kk][ei] = v;
                }
            }
#pragma unroll
            for (int ei = 0; ei < 4; ei++) {
                int n = lid + 32 * ei;
                uint16_t h[8], l[8];
#pragma unroll
                for (int kk = 0; kk < 8; kk++) bf16_split(r[kk][ei], h[kk], l[kk]);
                uint4 hv = make_uint4((uint32_t)h[0] | ((uint32_t)h[1] << 16),
                                      (uint32_t)h[2] | ((uint32_t)h[3] << 16),
                                      (uint32_t)h[4] | ((uint32_t)h[5] << 16),
                                      (uint32_t)h[6] | ((uint32_t)h[7] << 16));
                uint4 lv = make_uint4((uint32_t)l[0] | ((uint32_t)l[1] << 16),
                                      (uint32_t)l[2] | ((uint32_t)l[3] << 16),
                                      (uint32_t)l[4] | ((uint32_t)l[5] << 16),
                                      (uint32_t)l[6] | ((uint32_t)l[7] << 16));
                uint32_t off = (uint32_t)((n >> 3) * 1024 + (n & 7) * 128 + wid * 16);
                uint32_t sw = SW128(off);
                *(uint4*)(p + 32768 + sw) = hv;
                *(uint4*)(p + 49152 + sw) = lv;
            }
        }
        FENCE_PROXY_ASYNC_SHARED_CTA();
        __syncthreads();

        // ---- MMA for this chunk (warp 0, elected thread) ----
        if (wid == 0 && elect_one_pred()) {
            uint64_t ahi = desc_k_major(base);
            uint64_t alo = desc_k_major(base + 16384);
            uint64_t bhi = desc_k_major(base + 32768);
            uint64_t blo = desc_k_major(base + 49152);
#pragma unroll
            for (int s = 0; s < 4; s++) {   // K=16 per MMA, desc offsets 0,2,4,6
                uint64_t so = (uint64_t)(s * 2);
                mma_f16_ss(tmem, ahi + so, bhi + so, IDESC_BF16,
                           (c == 0 && s == 0) ? 0u : 1u);
                mma_f16_ss(tmem, ahi + so, blo + so, IDESC_BF16, 1u);
                mma_f16_ss(tmem, alo + so, bhi + so, IDESC_BF16, 1u);
            }
            TCGEN05_COMMIT(mbar);
        }
        // ALL threads wait for this chunk's MMA to finish before re-staging
        MBARRIER_WAIT_PARITY(mbar, c & 1);
    }

    TCGEN05_FENCE_AFTER();

    // epilogue: warps 0-3 read D (128x128 fp32) and store
    if (wid < 4) {
        const int m = wid * 32 + lid;
        float* op = Out + ((size_t)b * U_ + row0 + m) * L_ + col0;
#pragma unroll
        for (int j = 0; j < 4; j++) {
            uint32_t r32[32];
            TCGEN05_LD_32X32B_X32(r32, tmem + j * 32);
            TCGEN05_WAIT_LD();
            TCGEN05_FENCE_BEFORE();
#pragma unroll
            for (int q = 0; q < 8; q++) {
                float4 v = make_float4(__uint_as_float(r32[q * 4 + 0]),
                                       __uint_as_float(r32[q * 4 + 1]),
                                       __uint_as_float(r32[q * 4 + 2]),
                                       __uint_as_float(r32[q * 4 + 3]));
                *(float4*)(op + j * 32 + q * 4) = v;
            }
        }
    }
    __syncthreads();
    if (wid == 0) TCGEN05_DEALLOC(tmem, 512);
#else
    (void)W; (void)X1; (void)X2; (void)Out;
#endif
}

// ===========================================================================
// Fused masked ReLU attention (fp32, unchanged from R2 passing version)
// ===========================================================================
#define QS_OFF   0
#define KS_OFF   8192
#define KST_OFF  12288
#define SST_OFF  16640
#define MS_BYTE  100352
#define MS_STRIDE 68
#define CNT_OFF  27264
#define ATTN_SMEM_BYTES ((size_t)(27264 + 128) * 4)

__global__ __launch_bounds__(256, 2) void attn_kernel(
    const float* __restrict__ Q, const float* __restrict__ K,
    const int* __restrict__ mask, float* __restrict__ C)
{
    extern __shared__ float sm[];
    float* Qs  = sm + QS_OFF;
    float* Ks  = sm + KS_OFF;
    float* Kst = sm + KST_OFF;
    float* Sst = sm + SST_OFF;
    uint8_t* Ms = (uint8_t*)sm + MS_BYTE;
    int* cnts = (int*)(sm + CNT_OFF);

    const int b  = blockIdx.z;
    const int h  = blockIdx.x;
    const int x0 = blockIdx.y * 128;
    const int tid = threadIdx.x;
    const int tx = tid & 15;
    const int ty = tid >> 4;

    if (tid < 128) cnts[tid] = 0;

    const float* Qbase = Q + ((size_t)(b * U_ + h * D_)) * L_ + x0;
#pragma unroll
    for (int r = 0; r < 8; r++) {
        int idx = tid + r * 256;
        int kd = idx >> 5;
        int x4 = (idx & 31) << 2;
        float4 v = *(const float4*)(Qbase + (size_t)kd * L_ + x4);
        v.x *= SCALE_; v.y *= SCALE_; v.z *= SCALE_; v.w *= SCALE_;
        *(float4*)&Qs[kd * 128 + x4] = v;
    }

    float cc[4][2][4];
#pragma unroll
    for (int a = 0; a < 4; a++)
#pragma unroll
        for (int hx = 0; hx < 2; hx++)
#pragma unroll
            for (int j = 0; j < 4; j++) cc[a][hx][j] = 0.f;

    int cnt[2][4];
#pragma unroll
    for (int hx = 0; hx < 2; hx++)
#pragma unroll
        for (int i = 0; i < 4; i++) cnt[hx][i] = 0;

    const float* Kbase = K + ((size_t)(b * U_ + h * D_)) * L_;
    const int*   Mbase = mask + ((size_t)b * L_ + x0) * L_;

    const int xs = tx * 4;
    const int ys = ty * 4;

    for (int yt = 0; yt < L_ / 64; yt++) {
        const int y0 = yt * 64;
        __syncthreads();

#pragma unroll
        for (int r = 0; r < 4; r++) {
            int idx = tid + r * 256;
            int kd = idx >> 4;
            int y4 = (idx & 15) << 2;
            float4 v = *(const float4*)(Kbase + (size_t)kd * L_ + y0 + y4);
            *(float4*)&Ks[kd * 64 + y4] = v;
            Kst[(y4 + 0) * 68 + kd] = v.x;
            Kst[(y4 + 1) * 68 + kd] = v.y;
            Kst[(y4 + 2) * 68 + kd] = v.z;
            Kst[(y4 + 3) * 68 + kd] = v.w;
        }
#pragma unroll
        for (int r = 0; r < 8; r++) {
            int idx = tid + r * 256;
            int xr = idx >> 4;
            int yw = idx & 15;
            int4 m = *(const int4*)(Mbase + (size_t)xr * L_ + y0 + yw * 4);
            uint32_t packed = (m.x != 0 ? 1u : 0u)
                            | (m.y != 0 ? 1u << 8 : 0u)
                            | (m.z != 0 ? 1u << 16 : 0u)
                            | (m.w != 0 ? 1u << 24 : 0u);
            *(uint32_t*)(Ms + xr * MS_STRIDE + yw * 4) = packed;
        }
        __syncthreads();

        float s[2][4][4];
#pragma unroll
        for (int hx = 0; hx < 2; hx++)
#pragma unroll
            for (int i = 0; i < 4; i++)
#pragma unroll
                for (int j = 0; j < 4; j++) s[hx][i][j] = 0.f;

#pragma unroll 4
        for (int kd = 0; kd < 64; kd++) {
            float4 q0 = *(const float4*)&Qs[kd * 128 + xs];
            float4 q1 = *(const float4*)&Qs[kd * 128 + xs + 64];
            float4 kv = *(const float4*)&Ks[kd * 64 + ys];
            float qa[2][4] = {{q0.x, q0.y, q0.z, q0.w}, {q1.x, q1.y, q1.z, q1.w}};
            float kb[4] = {kv.x, kv.y, kv.z, kv.w};
#pragma unroll
            for (int hx = 0; hx < 2; hx++)
#pragma unroll
                for (int i = 0; i < 4; i++)
#pragma unroll
                    for (int j = 0; j < 4; j++)
                        s[hx][i][j] = fmaf(qa[hx][i], kb[j], s[hx][i][j]);
        }

#pragma unroll
        for (int hx = 0; hx < 2; hx++)
#pragma unroll
            for (int i = 0; i < 4; i++) {
                int xr = xs + hx * 64 + i;
                uint32_t mw = *(const uint32_t*)(Ms + xr * MS_STRIDE + ys);
#pragma unroll
                for (int j = 0; j < 4; j++) {
                    uint32_t mb = (mw >> (8 * j)) & 0xFFu;
                    float v = s[hx][i][j];
                    v = v > 0.f ? v : 0.f;
                    v = mb ? v : 0.f;
                    s[hx][i][j] = v;
                    cnt[hx][i] += mb ? 1 : 0;
                }
            }

#pragma unroll
        for (int j = 0; j < 4; j++)
#pragma unroll
            for (int hx = 0; hx < 2; hx++) {
                float4 v = make_float4(s[hx][0][j], s[hx][1][j], s[hx][2][j], s[hx][3][j]);
                *(float4*)&Sst[(ys + j) * 132 + xs + hx * 64] = v;
            }
        __syncthreads();

#pragma unroll 4
        for (int yj = 0; yj < 64; yj++) {
            float4 kv = *(const float4*)&Kst[yj * 68 + ty * 4];
            float4 s0 = *(const float4*)&Sst[yj * 132 + tx * 4];
            float4 s1 = *(const float4*)&Sst[yj * 132 + tx * 4 + 64];
            float ka[4] = {kv.x, kv.y, kv.z, kv.w};
            float sb[2][4] = {{s0.x, s0.y, s0.z, s0.w}, {s1.x, s1.y, s1.z, s1.w}};
#pragma unroll
            for (int a = 0; a < 4; a++)
#pragma unroll
                for (int hx = 0; hx < 2; hx++)
#pragma unroll
                    for (int j = 0; j < 4; j++)
                        cc[a][hx][j] = fmaf(ka[a], sb[hx][j], cc[a][hx][j]);
        }
    }

#pragma unroll
    for (int hx = 0; hx < 2; hx++)
#pragma unroll
        for (int i = 0; i < 4; i++)
            atomicAdd(&cnts[xs + hx * 64 + i], cnt[hx][i]);
    __syncthreads();

    float inv[2][4];
#pragma unroll
    for (int hx = 0; hx < 2; hx++)
#pragma unroll
        for (int j = 0; j < 4; j++) {
            int c = cnts[xs + hx * 64 + j];
            inv[hx][j] = 1.0f / (float)(c > 0 ? c : 1);
        }

    float* Cbase = C + ((size_t)(b * U_ + h * D_ + ty * 4)) * L_ + x0;
#pragma unroll
    for (int a = 0; a < 4; a++)
#pragma unroll
        for (int hx = 0; hx < 2; hx++) {
            float4 v = make_float4(cc[a][hx][0] * inv[hx][0], cc[a][hx][1] * inv[hx][1],
                                   cc[a][hx][2] * inv[hx][2], cc[a][hx][3] * inv[hx][3]);
            *(float4*)(Cbase + (size_t)a * L_ + hx * 64 + tx * 4) = v;
        }
}

// ---------------------------------------------------------------------------
extern "C" void kernel_launch(void* const* d_in, const int* in_sizes, int n_in,
                              void* d_out, int out_size)
{
    const float* x  = (const float*)d_in[0];
    const float* y  = (const float*)d_in[1];
    const int*   mk = (const int*)d_in[2];
    const float* wq = (const float*)d_in[3];
    const float* wk = (const float*)d_in[4];
    const float* wo = (const float*)d_in[5];
    float* out = (float*)d_out;

    float *Qp, *Kp, *Cp;
    cudaGetSymbolAddress((void**)&Qp, g_Q);
    cudaGetSymbolAddress((void**)&Kp, g_K);
    cudaGetSymbolAddress((void**)&Cp, g_C);

    cudaFuncSetAttribute(tc_gemm<false>, cudaFuncAttributeMaxDynamicSharedMemorySize,
                         TCG_SMEM_BYTES);
    cudaFuncSetAttribute(tc_gemm<true>, cudaFuncAttributeMaxDynamicSharedMemorySize,
                         TCG_SMEM_BYTES);
    cudaFuncSetAttribute(attn_kernel, cudaFuncAttributeMaxDynamicSharedMemorySize,
                         (int)ATTN_SMEM_BYTES);

    dim3 gg(L_ / 128, U_ / 128, B_);   // (8, 4, 16)
    tc_gemm<false><<<gg, 256, TCG_SMEM_BYTES>>>(wq, x, nullptr, Qp);
    tc_gemm<false><<<gg, 256, TCG_SMEM_BYTES>>>(wk, y, nullptr, Kp);
    attn_kernel<<<dim3(H_, L_ / 128, B_), 256, ATTN_SMEM_BYTES>>>(Qp, Kp, mk, Cp);
    tc_gemm<true><<<gg, 256, TCG_SMEM_BYTES>>>(wo, Qp, Cp, out);
}

// round 9
// speedup vs baseline: 1.9997x; 1.5200x over previous
#include <cuda_runtime.h>
#include <cuda_bf16.h>
#include <cstdint>
#include <cstddef>

// Problem constants
#define B_  16
#define U_  512
#define L_  1024
#define H_  8
#define D_  64
#define SCALE_ 0.125f   // 1/sqrt(64)

// Scratch (device globals — allocation-free rule).
__device__ __align__(256) float g_Q[(size_t)B_ * U_ * L_];
__device__ __align__(256) float g_K[(size_t)B_ * U_ * L_];
__device__ __align__(256) float g_C[(size_t)B_ * U_ * L_];

// ===========================================================================
// Arch gating: tcgen05 is arch-specific; the harness also builds a non-'a'
// target where these instructions are illegal. Stub tcgen05 bodies there.
// ===========================================================================
#if defined(__CUDA_ARCH_FEAT_SM103_ALL) || defined(__CUDA_ARCH_FEAT_SM100_ALL) || \
    defined(__CUDA_ARCH_FAMILY_SPECIFIC__) || defined(__CUDA_ARCH_SPECIFIC__)
#define TC_OK 1
#else
#define TC_OK 0
#endif

__device__ __forceinline__ uint32_t smem_to_u32(const void* p) {
    uint32_t a;
    asm("{ .reg .u64 t; cvta.to.shared.u64 t, %1; cvt.u32.u64 %0, t; }" : "=r"(a) : "l"(p));
    return a;
}
#define MBARRIER_INIT(mbar, count) \
    asm volatile("mbarrier.init.shared.b64 [%0], %1;" \
                 :: "r"((uint32_t)(mbar)), "r"((uint32_t)(count)) : "memory")
#define MBARRIER_WAIT_PARITY(mbar, parity) do {                                   \
    uint32_t _m = (uint32_t)(mbar); uint32_t _p = (uint32_t)(parity);             \
    asm volatile("{\n\t.reg .pred P1;\n\t"                                        \
        "WAIT_LOOP_%=:\n\t"                                                        \
        "mbarrier.try_wait.parity.acquire.cta.shared::cta.b64 P1, [%0], %1, 0x989680;\n\t" \
        "@P1 bra.uni WAIT_DONE_%=;\n\t"                                            \
        "bra.uni WAIT_LOOP_%=;\n\t"                                                \
        "WAIT_DONE_%=:\n\t}" :: "r"(_m), "r"(_p) : "memory");                      \
} while (0)
#define FENCE_PROXY_ASYNC_SHARED_CTA() asm volatile("fence.proxy.async.shared::cta;" ::: "memory")

#if TC_OK
__device__ __forceinline__ uint32_t elect_one_pred() {
    uint32_t pred;
    asm volatile("{\n\t.reg .pred p;\n\telect.sync _|p, 0xFFFFFFFF;\n\tselp.b32 %0, 1, 0, p;\n\t}"
                 : "=r"(pred));
    return pred;
}
#define TCGEN05_ALLOC(smem_result_addr, nCols) \
    asm volatile("tcgen05.alloc.cta_group::1.sync.aligned.shared::cta.b32 [%0], %1;" \
                 :: "r"((uint32_t)(smem_result_addr)), "r"((uint32_t)(nCols)) : "memory")
#define TCGEN05_DEALLOC(tmem_addr, nCols) \
    asm volatile("tcgen05.dealloc.cta_group::1.sync.aligned.b32 %0, %1;" \
                 :: "r"(tmem_addr), "r"((uint32_t)(nCols)))
#define TCGEN05_COMMIT(mbar) \
    asm volatile("tcgen05.commit.cta_group::1.mbarrier::arrive::one.shared::cluster.b64 [%0];" \
                 :: "r"((uint32_t)(mbar)) : "memory")
#define TCGEN05_FENCE_BEFORE() asm volatile("tcgen05.fence::before_thread_sync;" ::: "memory")
#define TCGEN05_FENCE_AFTER()  asm volatile("tcgen05.fence::after_thread_sync;"  ::: "memory")
#define TCGEN05_WAIT_LD()      asm volatile("tcgen05.wait::ld.sync.aligned;"     ::: "memory")
#define TCGEN05_LD_32X32B_X32(r, tmem_addr) \
    asm volatile( \
        "tcgen05.ld.sync.aligned.32x32b.x32.b32 " \
        "{%0, %1, %2, %3, %4, %5, %6, %7, " \
        " %8, %9, %10, %11, %12, %13, %14, %15, " \
        " %16, %17, %18, %19, %20, %21, %22, %23, " \
        " %24, %25, %26, %27, %28, %29, %30, %31}, [%32];" \
        : "=r"((r)[0]),  "=r"((r)[1]),  "=r"((r)[2]),  "=r"((r)[3]), \
          "=r"((r)[4]),  "=r"((r)[5]),  "=r"((r)[6]),  "=r"((r)[7]), \
          "=r"((r)[8]),  "=r"((r)[9]),  "=r"((r)[10]), "=r"((r)[11]), \
          "=r"((r)[12]), "=r"((r)[13]), "=r"((r)[14]), "=r"((r)[15]), \
          "=r"((r)[16]), "=r"((r)[17]), "=r"((r)[18]), "=r"((r)[19]), \
          "=r"((r)[20]), "=r"((r)[21]), "=r"((r)[22]), "=r"((r)[23]), \
          "=r"((r)[24]), "=r"((r)[25]), "=r"((r)[26]), "=r"((r)[27]), \
          "=r"((r)[28]), "=r"((r)[29]), "=r"((r)[30]), "=r"((r)[31]) \
        : "r"(tmem_addr))

// SS-mode f16-kind MMA (bf16 operands via idesc), cta_group::1
__device__ __forceinline__ void mma_f16_ss(uint32_t d_tmem, uint64_t a_desc,
                                           uint64_t b_desc, uint32_t idesc,
                                           uint32_t enable) {
    asm volatile(
        "{\n\t"
        ".reg .pred p;\n\t"
        "setp.ne.u32 p, %5, 0;\n\t"
        "tcgen05.mma.cta_group::1.kind::f16 [%0], %1, %2, %3, {%4, %4, %4, %4}, p;\n\t"
        "}"
        :: "r"(d_tmem), "l"(a_desc), "l"(b_desc), "r"(idesc), "r"(0u), "r"(enable)
        : "memory");
}
#endif  // TC_OK

// K-major SW128 descriptor: LBO=1 (16B), SBO=64 (1024B), version=1, SW128=2
__device__ __forceinline__ uint64_t desc_k_major(uint32_t addr) {
    return ((uint64_t)(addr >> 4) & 0x3FFF)
         | (1ull << 16) | (64ull << 32) | (1ull << 46) | (2ull << 61);
}

#define SW128(off) ((off) ^ (((off) >> 3) & 0x70))

// idesc: dtype F32 (1<<4) | atype BF16 (1<<7) | btype BF16 (1<<10)
//        | (N/8)<<17 | (M=128/16)<<24
#define IDESC_BF16_N128 0x8200490u
#define IDESC_BF16_N64  0x8100490u

// split: hi = rn-bf16(x), lo = rn-bf16(x - hi); error ~2^-18 per product
__device__ __forceinline__ void bf16_split(float x, uint16_t& hi, uint16_t& lo) {
    __nv_bfloat16 h = __float2bfloat16(x);
    float r = x - __bfloat162float(h);
    __nv_bfloat16 l = __float2bfloat16(r);
    hi = __bfloat16_as_ushort(h);
    lo = __bfloat16_as_ushort(l);
}

// ===========================================================================
// tcgen05 split-bf16 channel-mix GEMM (R8 proven, unchanged):
// ===========================================================================
#define TCG_SMEM_BYTES 66688

template <bool FUSE>
__global__ __launch_bounds__(256, 1) __cluster_dims__(1, 1, 1) void tc_gemm(
    const float* __restrict__ W,
    const float* __restrict__ X1,
    const float* __restrict__ X2,
    float* __restrict__ Out)
{
#if TC_OK
    extern __shared__ uint8_t dsm[];
    const uint32_t raw  = smem_to_u32(dsm);
    const uint32_t base = (raw + 1023u) & ~1023u;
    uint8_t* p = dsm + (base - raw);

    const uint32_t ctrl = base + 65536;
    const uint32_t mbar = ctrl + 8;

    const int b    = blockIdx.z;
    const int row0 = blockIdx.y * 128;
    const int col0 = blockIdx.x * 128;
    const int tid  = threadIdx.x;
    const int wid  = tid >> 5;
    const int lid  = tid & 31;

    if (wid == 0) TCGEN05_ALLOC(ctrl, 512);
    if (tid == 0) MBARRIER_INIT(mbar, 1);
    __syncthreads();
    uint32_t tmem;
    asm volatile("ld.shared.b32 %0, [%1];" : "=r"(tmem) : "r"(ctrl));

    const float* Wb  = W + (size_t)row0 * U_;
    const float* X1b = X1 + (size_t)b * U_ * L_ + col0;
    const float* X2b = FUSE ? (X2 + (size_t)b * U_ * L_ + col0) : nullptr;

    const int NC = U_ / 64;
    for (int c = 0; c < NC; c++) {
        const int k0 = c * 64;
#pragma unroll
        for (int t = 0; t < 8; t++) {
            int idx = tid + t * 256;
            int m  = idx >> 4;
            int k4 = (idx & 15) << 2;
            float4 v = *(const float4*)(Wb + (size_t)m * U_ + k0 + k4);
            uint16_t h0, l0, h1, l1, h2, l2, h3, l3;
            bf16_split(v.x, h0, l0); bf16_split(v.y, h1, l1);
            bf16_split(v.z, h2, l2); bf16_split(v.w, h3, l3);
            uint2 hv = make_uint2((uint32_t)h0 | ((uint32_t)h1 << 16),
                                  (uint32_t)h2 | ((uint32_t)h3 << 16));
            uint2 lv = make_uint2((uint32_t)l0 | ((uint32_t)l1 << 16),
                                  (uint32_t)l2 | ((uint32_t)l3 << 16));
            uint32_t off = (uint32_t)((m >> 3) * 1024 + (m & 7) * 128 + k4 * 2);
            uint32_t sw = SW128(off);
            *(uint2*)(p + sw)         = hv;
            *(uint2*)(p + 16384 + sw) = lv;
        }
        {
            float r[8][4];
#pragma unroll
            for (int kk = 0; kk < 8; kk++) {
                const float* xr = X1b + (size_t)(k0 + wid * 8 + kk) * L_;
                const float* yr = FUSE ? (X2b + (size_t)(k0 + wid * 8 + kk) * L_) : nullptr;
#pragma unroll
                for (int ei = 0; ei < 4; ei++) {
                    int n = lid + 32 * ei;
                    float v = xr[n];
                    if (FUSE) v = 0.5f * (v + yr[n]);
                    r[kk][ei] = v;
                }
            }
#pragma unroll
            for (int ei = 0; ei < 4; ei++) {
                int n = lid + 32 * ei;
                uint16_t h[8], l[8];
#pragma unroll
                for (int kk = 0; kk < 8; kk++) bf16_split(r[kk][ei], h[kk], l[kk]);
                uint4 hv = make_uint4((uint32_t)h[0] | ((uint32_t)h[1] << 16),
                                      (uint32_t)h[2] | ((uint32_t)h[3] << 16),
                                      (uint32_t)h[4] | ((uint32_t)h[5] << 16),
                                      (uint32_t)h[6] | ((uint32_t)h[7] << 16));
                uint4 lv = make_uint4((uint32_t)l[0] | ((uint32_t)l[1] << 16),
                                      (uint32_t)l[2] | ((uint32_t)l[3] << 16),
                                      (uint32_t)l[4] | ((uint32_t)l[5] << 16),
                                      (uint32_t)l[6] | ((uint32_t)l[7] << 16));
                uint32_t off = (uint32_t)((n >> 3) * 1024 + (n & 7) * 128 + wid * 16);
                uint32_t sw = SW128(off);
                *(uint4*)(p + 32768 + sw) = hv;
                *(uint4*)(p + 49152 + sw) = lv;
            }
        }
        FENCE_PROXY_ASYNC_SHARED_CTA();
        __syncthreads();

        if (wid == 0 && elect_one_pred()) {
            uint64_t ahi = desc_k_major(base);
            uint64_t alo = desc_k_major(base + 16384);
            uint64_t bhi = desc_k_major(base + 32768);
            uint64_t blo = desc_k_major(base + 49152);
#pragma unroll
            for (int s = 0; s < 4; s++) {
                uint64_t so = (uint64_t)(s * 2);
                mma_f16_ss(tmem, ahi + so, bhi + so, IDESC_BF16_N128,
                           (c == 0 && s == 0) ? 0u : 1u);
                mma_f16_ss(tmem, ahi + so, blo + so, IDESC_BF16_N128, 1u);
                mma_f16_ss(tmem, alo + so, bhi + so, IDESC_BF16_N128, 1u);
            }
            TCGEN05_COMMIT(mbar);
        }
        MBARRIER_WAIT_PARITY(mbar, c & 1);
    }

    TCGEN05_FENCE_AFTER();

    if (wid < 4) {
        const int m = wid * 32 + lid;
        float* op = Out + ((size_t)b * U_ + row0 + m) * L_ + col0;
#pragma unroll
        for (int j = 0; j < 4; j++) {
            uint32_t r32[32];
            TCGEN05_LD_32X32B_X32(r32, tmem + j * 32);
            TCGEN05_WAIT_LD();
            TCGEN05_FENCE_BEFORE();
#pragma unroll
            for (int q = 0; q < 8; q++) {
                float4 v = make_float4(__uint_as_float(r32[q * 4 + 0]),
                                       __uint_as_float(r32[q * 4 + 1]),
                                       __uint_as_float(r32[q * 4 + 2]),
                                       __uint_as_float(r32[q * 4 + 3]));
                *(float4*)(op + j * 32 + q * 4) = v;
            }
        }
    }
    __syncthreads();
    if (wid == 0) TCGEN05_DEALLOC(tmem, 512);
#else
    (void)W; (void)X1; (void)X2; (void)Out;
#endif
}

// ===========================================================================
// tcgen05 attention: per CTA (b, h, 128 x-rows), 16 y-tiles of 64.
//   MMA1: S[x,y] = (scale*Q)^T K  (M=128,N=64,K=64), split-bf16 3-MMA
//   LDTM S -> relu+mask+count (lane owns row x) -> split-bf16 -> smem
//   MMA2: C^T[x,d] += S' * K     (M=128,N=64,K=64), accumulated in TMEM
// smem byte offsets (from 1KB-aligned base):
//   QHI 0 | QLO 16384 | KTHI 32768 | KTLO 40960 | KHI 49152 | KLO 57344
//   SHI 65536 | SLO 81920 | MS 98304 (128x68 bytes) | ctrl 107008
// ===========================================================================
#define AT_SMEM_BYTES 108576

__global__ __launch_bounds__(128, 1) __cluster_dims__(1, 1, 1) void attn_tc(
    const float* __restrict__ Q, const float* __restrict__ K,
    const int* __restrict__ mask, float* __restrict__ C)
{
#if TC_OK
    extern __shared__ uint8_t dsm[];
    const uint32_t raw  = smem_to_u32(dsm);
    const uint32_t base = (raw + 1023u) & ~1023u;
    uint8_t* p = dsm + (base - raw);

    const uint32_t QHI = base, QLO = base + 16384;
    const uint32_t KTHI = base + 32768, KTLO = base + 40960;
    const uint32_t KHI = base + 49152, KLO = base + 57344;
    const uint32_t SHI = base + 65536, SLO = base + 81920;
    uint8_t* Msp = p + 98304;
    const uint32_t ctrl = base + 107008;
    const uint32_t mbar = ctrl + 8;

    const int b  = blockIdx.z;
    const int h  = blockIdx.x;          // h fastest: mask tile L2 reuse
    const int x0 = blockIdx.y * 128;
    const int tid = threadIdx.x;
    const int wid = tid >> 5;
    const int lid = tid & 31;

    if (wid == 0) TCGEN05_ALLOC(ctrl, 512);
    if (tid == 0) MBARRIER_INIT(mbar, 1);
    __syncthreads();
    uint32_t tmem;
    asm volatile("ld.shared.b32 %0, [%1];" : "=r"(tmem) : "r"(ctrl));

    const float* Qb = Q + ((size_t)(b * U_ + h * D_)) * L_ + x0;
    const float* Kb = K + ((size_t)(b * U_ + h * D_)) * L_;
    const int*   Mb = mask + ((size_t)b * L_ + x0) * L_;

    // ---- stage Q^T [128x][64d] hi/lo (scale folded), once per CTA ----
    {
        float r[16][4];
#pragma unroll
        for (int kk = 0; kk < 16; kk++) {
            const float* qr = Qb + (size_t)(wid * 16 + kk) * L_;
#pragma unroll
            for (int ei = 0; ei < 4; ei++)
                r[kk][ei] = qr[lid + 32 * ei] * SCALE_;
        }
#pragma unroll
        for (int ei = 0; ei < 4; ei++) {
            int x = lid + 32 * ei;
            uint16_t hh[16], ll[16];
#pragma unroll
            for (int kk = 0; kk < 16; kk++) bf16_split(r[kk][ei], hh[kk], ll[kk]);
            uint32_t off = (uint32_t)((x >> 3) * 1024 + (x & 7) * 128 + wid * 32);
#pragma unroll
            for (int g = 0; g < 2; g++) {
                uint4 hv = make_uint4(
                    (uint32_t)hh[g*8+0] | ((uint32_t)hh[g*8+1] << 16),
                    (uint32_t)hh[g*8+2] | ((uint32_t)hh[g*8+3] << 16),
                    (uint32_t)hh[g*8+4] | ((uint32_t)hh[g*8+5] << 16),
                    (uint32_t)hh[g*8+6] | ((uint32_t)hh[g*8+7] << 16));
                uint4 lv = make_uint4(
                    (uint32_t)ll[g*8+0] | ((uint32_t)ll[g*8+1] << 16),
                    (uint32_t)ll[g*8+2] | ((uint32_t)ll[g*8+3] << 16),
                    (uint32_t)ll[g*8+4] | ((uint32_t)ll[g*8+5] << 16),
                    (uint32_t)ll[g*8+6] | ((uint32_t)ll[g*8+7] << 16));
                uint32_t sw = SW128(off + g * 16);
                *(uint4*)(p + (QHI - base) + sw) = hv;
                *(uint4*)(p + (QLO - base) + sw) = lv;
            }
        }
    }

    int cnt = 0;          // per-lane mask count for row x = wid*32+lid
    int ph = 0;           // mbarrier phase counter

    for (int yt = 0; yt < 16; yt++) {
        const int y0 = yt * 64;

        // ---- stage K^T [64y][64d] hi/lo ----
        {
            float r[16][2];
#pragma unroll
            for (int kk = 0; kk < 16; kk++) {
                const float* kr = Kb + (size_t)(wid * 16 + kk) * L_ + y0;
#pragma unroll
                for (int ei = 0; ei < 2; ei++)
                    r[kk][ei] = kr[lid + 32 * ei];
            }
#pragma unroll
            for (int ei = 0; ei < 2; ei++) {
                int y = lid + 32 * ei;
                uint16_t hh[16], ll[16];
#pragma unroll
                for (int kk = 0; kk < 16; kk++) bf16_split(r[kk][ei], hh[kk], ll[kk]);
                uint32_t off = (uint32_t)((y >> 3) * 1024 + (y & 7) * 128 + wid * 32);
#pragma unroll
                for (int g = 0; g < 2; g++) {
                    uint4 hv = make_uint4(
                        (uint32_t)hh[g*8+0] | ((uint32_t)hh[g*8+1] << 16),
                        (uint32_t)hh[g*8+2] | ((uint32_t)hh[g*8+3] << 16),
                        (uint32_t)hh[g*8+4] | ((uint32_t)hh[g*8+5] << 16),
                        (uint32_t)hh[g*8+6] | ((uint32_t)hh[g*8+7] << 16));
                    uint4 lv = make_uint4(
                        (uint32_t)ll[g*8+0] | ((uint32_t)ll[g*8+1] << 16),
                        (uint32_t)ll[g*8+2] | ((uint32_t)ll[g*8+3] << 16),
                        (uint32_t)ll[g*8+4] | ((uint32_t)ll[g*8+5] << 16),
                        (uint32_t)ll[g*8+6] | ((uint32_t)ll[g*8+7] << 16));
                    uint32_t sw = SW128(off + g * 16);
                    *(uint4*)(p + (KTHI - base) + sw) = hv;
                    *(uint4*)(p + (KTLO - base) + sw) = lv;
                }
            }
        }
        // ---- stage K [64d][64y] hi/lo (natural layout) ----
#pragma unroll
        for (int t = 0; t < 8; t++) {
            int idx = tid + t * 128;
            int d  = idx >> 4;
            int y4 = (idx & 15) << 2;
            float4 v = *(const float4*)(Kb + (size_t)d * L_ + y0 + y4);
            uint16_t h0, l0, h1, l1, h2, l2, h3, l3;
            bf16_split(v.x, h0, l0); bf16_split(v.y, h1, l1);
            bf16_split(v.z, h2, l2); bf16_split(v.w, h3, l3);
            uint2 hv = make_uint2((uint32_t)h0 | ((uint32_t)h1 << 16),
                                  (uint32_t)h2 | ((uint32_t)h3 << 16));
            uint2 lv = make_uint2((uint32_t)l0 | ((uint32_t)l1 << 16),
                                  (uint32_t)l2 | ((uint32_t)l3 << 16));
            uint32_t off = (uint32_t)((d >> 3) * 1024 + (d & 7) * 128 + y4 * 2);
            uint32_t sw = SW128(off);
            *(uint2*)(p + (KHI - base) + sw) = hv;
            *(uint2*)(p + (KLO - base) + sw) = lv;
        }
        // ---- stage mask tile (128x x 64 int32 -> packed bytes) ----
#pragma unroll
        for (int t = 0; t < 16; t++) {
            int idx = tid + t * 128;
            int xr = idx >> 4;
            int yw = idx & 15;
            int4 m = *(const int4*)(Mb + (size_t)xr * L_ + y0 + yw * 4);
            uint32_t packed = (m.x != 0 ? 1u : 0u)
                            | (m.y != 0 ? 1u << 8 : 0u)
                            | (m.z != 0 ? 1u << 16 : 0u)
                            | (m.w != 0 ? 1u << 24 : 0u);
            *(uint32_t*)(Msp + xr * 68 + yw * 4) = packed;
        }
        FENCE_PROXY_ASYNC_SHARED_CTA();
        __syncthreads();

        // ---- MMA1: S = Q^T K ----
        if (wid == 0 && elect_one_pred()) {
            uint64_t ah = desc_k_major(QHI), al = desc_k_major(QLO);
            uint64_t bh = desc_k_major(KTHI), bl = desc_k_major(KTLO);
#pragma unroll
            for (int s = 0; s < 4; s++) {
                uint64_t so = (uint64_t)(s * 2);
                mma_f16_ss(tmem, ah + so, bh + so, IDESC_BF16_N64, s > 0 ? 1u : 0u);
                mma_f16_ss(tmem, ah + so, bl + so, IDESC_BF16_N64, 1u);
                mma_f16_ss(tmem, al + so, bh + so, IDESC_BF16_N64, 1u);
            }
            TCGEN05_COMMIT(mbar);
        }
        MBARRIER_WAIT_PARITY(mbar, ph & 1); ph++;
        TCGEN05_FENCE_AFTER();

        // ---- LDTM S, relu+mask+count, split-bf16, stage S' ----
        {
            uint32_t s0[32], s1[32];
            TCGEN05_LD_32X32B_X32(s0, tmem + 0);
            TCGEN05_LD_32X32B_X32(s1, tmem + 32);
            TCGEN05_WAIT_LD();
            TCGEN05_FENCE_BEFORE();
            const int x = wid * 32 + lid;
            uint32_t mw[16];
#pragma unroll
            for (int i = 0; i < 16; i++)
                mw[i] = *(uint32_t*)(Msp + x * 68 + i * 4);
            uint16_t hh[64], ll[64];
#pragma unroll
            for (int j = 0; j < 64; j++) {
                float v = __uint_as_float(j < 32 ? s0[j] : s1[j - 32]);
                v = v > 0.f ? v : 0.f;
                uint32_t mb = (mw[j >> 2] >> ((j & 3) * 8)) & 0xFFu;
                v = mb ? v : 0.f;
                cnt += mb ? 1 : 0;
                bf16_split(v, hh[j], ll[j]);
            }
            uint32_t off = (uint32_t)((x >> 3) * 1024 + (x & 7) * 128);
#pragma unroll
            for (int g = 0; g < 8; g++) {
                uint4 hv = make_uint4(
                    (uint32_t)hh[g*8+0] | ((uint32_t)hh[g*8+1] << 16),
                    (uint32_t)hh[g*8+2] | ((uint32_t)hh[g*8+3] << 16),
                    (uint32_t)hh[g*8+4] | ((uint32_t)hh[g*8+5] << 16),
                    (uint32_t)hh[g*8+6] | ((uint32_t)hh[g*8+7] << 16));
                uint4 lv = make_uint4(
                    (uint32_t)ll[g*8+0] | ((uint32_t)ll[g*8+1] << 16),
                    (uint32_t)ll[g*8+2] | ((uint32_t)ll[g*8+3] << 16),
                    (uint32_t)ll[g*8+4] | ((uint32_t)ll[g*8+5] << 16),
                    (uint32_t)ll[g*8+6] | ((uint32_t)ll[g*8+7] << 16));
                uint32_t sw = SW128(off + g * 16);
                *(uint4*)(p + (SHI - base) + sw) = hv;
                *(uint4*)(p + (SLO - base) + sw) = lv;
            }
        }
        FENCE_PROXY_ASYNC_SHARED_CTA();
        __syncthreads();

        // ---- MMA2: C^T[x,d] += S' K ----
        if (wid == 0 && elect_one_pred()) {
            uint64_t ah = desc_k_major(SHI), al = desc_k_major(SLO);
            uint64_t bh = desc_k_major(KHI), bl = desc_k_major(KLO);
#pragma unroll
            for (int s = 0; s < 4; s++) {
                uint64_t so = (uint64_t)(s * 2);
                mma_f16_ss(tmem + 64, ah + so, bh + so, IDESC_BF16_N64,
                           (yt == 0 && s == 0) ? 0u : 1u);
                mma_f16_ss(tmem + 64, ah + so, bl + so, IDESC_BF16_N64, 1u);
                mma_f16_ss(tmem + 64, al + so, bh + so, IDESC_BF16_N64, 1u);
            }
            TCGEN05_COMMIT(mbar);
        }
        MBARRIER_WAIT_PARITY(mbar, ph & 1); ph++;
    }

    TCGEN05_FENCE_AFTER();

    // ---- epilogue: C^T[x][d] / max(cnt,1), transpose via smem, store ----
    {
        uint32_t c0[32], c1[32];
        TCGEN05_LD_32X32B_X32(c0, tmem + 64);
        TCGEN05_LD_32X32B_X32(c1, tmem + 96);
        TCGEN05_WAIT_LD();
        TCGEN05_FENCE_BEFORE();
        const int x = wid * 32 + lid;
        float inv = 1.0f / (float)(cnt > 0 ? cnt : 1);
        float* scr = (float*)p;   // reuse Q/KT region (done with it)
        __syncthreads();          // all warps past final smem reads of loop
#pragma unroll
        for (int j = 0; j < 64; j++) {
            float v = __uint_as_float(j < 32 ? c0[j] : c1[j - 32]) * inv;
            scr[x * 68 + j] = v;
        }
        __syncthreads();
        float* Cb = C + ((size_t)(b * U_ + h * D_)) * L_ + x0;
#pragma unroll
        for (int t = 0; t < 16; t++) {
            int idx = tid + t * 128;
            int d  = idx >> 5;
            int x4 = (idx & 31) << 2;
            float4 v = make_float4(scr[(x4 + 0) * 68 + d], scr[(x4 + 1) * 68 + d],
                                   scr[(x4 + 2) * 68 + d], scr[(x4 + 3) * 68 + d]);
            *(float4*)(Cb + (size_t)d * L_ + x4) = v;
        }
    }
    __syncthreads();
    if (wid == 0) TCGEN05_DEALLOC(tmem, 512);
#else
    (void)Q; (void)K; (void)mask; (void)C;
#endif
}

// ---------------------------------------------------------------------------
extern "C" void kernel_launch(void* const* d_in, const int* in_sizes, int n_in,
                              void* d_out, int out_size)
{
    const float* x  = (const float*)d_in[0];
    const float* y  = (const float*)d_in[1];
    const int*   mk = (const int*)d_in[2];
    const float* wq = (const float*)d_in[3];
    const float* wk = (const float*)d_in[4];
    const float* wo = (const float*)d_in[5];
    float* out = (float*)d_out;

    float *Qp, *Kp, *Cp;
    cudaGetSymbolAddress((void**)&Qp, g_Q);
    cudaGetSymbolAddress((void**)&Kp, g_K);
    cudaGetSymbolAddress((void**)&Cp, g_C);

    cudaFuncSetAttribute(tc_gemm<false>, cudaFuncAttributeMaxDynamicSharedMemorySize,
                         TCG_SMEM_BYTES);
    cudaFuncSetAttribute(tc_gemm<true>, cudaFuncAttributeMaxDynamicSharedMemorySize,
                         TCG_SMEM_BYTES);
    cudaFuncSetAttribute(attn_tc, cudaFuncAttributeMaxDynamicSharedMemorySize,
                         AT_SMEM_BYTES);

    dim3 gg(L_ / 128, U_ / 128, B_);   // (8, 4, 16)
    tc_gemm<false><<<gg, 256, TCG_SMEM_BYTES>>>(wq, x, nullptr, Qp);
    tc_gemm<false><<<gg, 256, TCG_SMEM_BYTES>>>(wk, y, nullptr, Kp);
    attn_tc<<<dim3(H_, L_ / 128, B_), 128, AT_SMEM_BYTES>>>(Qp, Kp, mk, Cp);
    tc_gemm<true><<<gg, 256, TCG_SMEM_BYTES>>>(wo, Qp, Cp, out);
}

// round 10
// speedup vs baseline: 2.3344x; 1.1674x over previous
#include <cuda_runtime.h>
#include <cuda_bf16.h>
#include <cstdint>
#include <cstddef>

// Problem constants
#define B_  16
#define U_  512
#define L_  1024
#define H_  8
#define D_  64
#define SCALE_ 0.125f   // 1/sqrt(64)

// Scratch (device globals — allocation-free rule).
__device__ __align__(256) float g_Q[(size_t)B_ * U_ * L_];
__device__ __align__(256) float g_K[(size_t)B_ * U_ * L_];
__device__ __align__(256) float g_C[(size_t)B_ * U_ * L_];

// ===========================================================================
// Arch gating
// ===========================================================================
#if defined(__CUDA_ARCH_FEAT_SM103_ALL) || defined(__CUDA_ARCH_FEAT_SM100_ALL) || \
    defined(__CUDA_ARCH_FAMILY_SPECIFIC__) || defined(__CUDA_ARCH_SPECIFIC__)
#define TC_OK 1
#else
#define TC_OK 0
#endif

__device__ __forceinline__ uint32_t smem_to_u32(const void* p) {
    uint32_t a;
    asm("{ .reg .u64 t; cvta.to.shared.u64 t, %1; cvt.u32.u64 %0, t; }" : "=r"(a) : "l"(p));
    return a;
}
#define MBARRIER_INIT(mbar, count) \
    asm volatile("mbarrier.init.shared.b64 [%0], %1;" \
                 :: "r"((uint32_t)(mbar)), "r"((uint32_t)(count)) : "memory")
#define MBARRIER_WAIT_PARITY(mbar, parity) do {                                   \
    uint32_t _m = (uint32_t)(mbar); uint32_t _p = (uint32_t)(parity);             \
    asm volatile("{\n\t.reg .pred P1;\n\t"                                        \
        "WAIT_LOOP_%=:\n\t"                                                        \
        "mbarrier.try_wait.parity.acquire.cta.shared::cta.b64 P1, [%0], %1, 0x989680;\n\t" \
        "@P1 bra.uni WAIT_DONE_%=;\n\t"                                            \
        "bra.uni WAIT_LOOP_%=;\n\t"                                                \
        "WAIT_DONE_%=:\n\t}" :: "r"(_m), "r"(_p) : "memory");                      \
} while (0)
#define FENCE_PROXY_ASYNC_SHARED_CTA() asm volatile("fence.proxy.async.shared::cta;" ::: "memory")

#if TC_OK
__device__ __forceinline__ uint32_t elect_one_pred() {
    uint32_t pred;
    asm volatile("{\n\t.reg .pred p;\n\telect.sync _|p, 0xFFFFFFFF;\n\tselp.b32 %0, 1, 0, p;\n\t}"
                 : "=r"(pred));
    return pred;
}
#define TCGEN05_ALLOC(smem_result_addr, nCols) \
    asm volatile("tcgen05.alloc.cta_group::1.sync.aligned.shared::cta.b32 [%0], %1;" \
                 :: "r"((uint32_t)(smem_result_addr)), "r"((uint32_t)(nCols)) : "memory")
#define TCGEN05_DEALLOC(tmem_addr, nCols) \
    asm volatile("tcgen05.dealloc.cta_group::1.sync.aligned.b32 %0, %1;" \
                 :: "r"(tmem_addr), "r"((uint32_t)(nCols)))
#define TCGEN05_COMMIT(mbar) \
    asm volatile("tcgen05.commit.cta_group::1.mbarrier::arrive::one.shared::cluster.b64 [%0];" \
                 :: "r"((uint32_t)(mbar)) : "memory")
#define TCGEN05_FENCE_BEFORE() asm volatile("tcgen05.fence::before_thread_sync;" ::: "memory")
#define TCGEN05_FENCE_AFTER()  asm volatile("tcgen05.fence::after_thread_sync;"  ::: "memory")
#define TCGEN05_WAIT_LD()      asm volatile("tcgen05.wait::ld.sync.aligned;"     ::: "memory")
#define TCGEN05_LD_32X32B_X32(r, tmem_addr) \
    asm volatile( \
        "tcgen05.ld.sync.aligned.32x32b.x32.b32 " \
        "{%0, %1, %2, %3, %4, %5, %6, %7, " \
        " %8, %9, %10, %11, %12, %13, %14, %15, " \
        " %16, %17, %18, %19, %20, %21, %22, %23, " \
        " %24, %25, %26, %27, %28, %29, %30, %31}, [%32];" \
        : "=r"((r)[0]),  "=r"((r)[1]),  "=r"((r)[2]),  "=r"((r)[3]), \
          "=r"((r)[4]),  "=r"((r)[5]),  "=r"((r)[6]),  "=r"((r)[7]), \
          "=r"((r)[8]),  "=r"((r)[9]),  "=r"((r)[10]), "=r"((r)[11]), \
          "=r"((r)[12]), "=r"((r)[13]), "=r"((r)[14]), "=r"((r)[15]), \
          "=r"((r)[16]), "=r"((r)[17]), "=r"((r)[18]), "=r"((r)[19]), \
          "=r"((r)[20]), "=r"((r)[21]), "=r"((r)[22]), "=r"((r)[23]), \
          "=r"((r)[24]), "=r"((r)[25]), "=r"((r)[26]), "=r"((r)[27]), \
          "=r"((r)[28]), "=r"((r)[29]), "=r"((r)[30]), "=r"((r)[31]) \
        : "r"(tmem_addr))

__device__ __forceinline__ void mma_f16_ss(uint32_t d_tmem, uint64_t a_desc,
                                           uint64_t b_desc, uint32_t idesc,
                                           uint32_t enable) {
    asm volatile(
        "{\n\t"
        ".reg .pred p;\n\t"
        "setp.ne.u32 p, %5, 0;\n\t"
        "tcgen05.mma.cta_group::1.kind::f16 [%0], %1, %2, %3, {%4, %4, %4, %4}, p;\n\t"
        "}"
        :: "r"(d_tmem), "l"(a_desc), "l"(b_desc), "r"(idesc), "r"(0u), "r"(enable)
        : "memory");
}
#endif  // TC_OK

// K-major SW128 descriptor
__device__ __forceinline__ uint64_t desc_k_major(uint32_t addr) {
    return ((uint64_t)(addr >> 4) & 0x3FFF)
         | (1ull << 16) | (64ull << 32) | (1ull << 46) | (2ull << 61);
}

#define SW128(off) ((off) ^ (((off) >> 3) & 0x70))

#define IDESC_BF16_N128 0x8200490u
#define IDESC_BF16_N64  0x8100490u

__device__ __forceinline__ void bf16_split(float x, uint16_t& hi, uint16_t& lo) {
    __nv_bfloat16 h = __float2bfloat16(x);
    float r = x - __bfloat162float(h);
    __nv_bfloat16 l = __float2bfloat16(r);
    hi = __bfloat16_as_ushort(h);
    lo = __bfloat16_as_ushort(l);
}

// ===========================================================================
// tcgen05 split-bf16 channel-mix GEMM — DOUBLE-BUFFERED (R8 scaffolding):
//   buffers at base + beta*65536; Ahi 0 | Alo 16384 | Bhi 32768 | Blo 49152
// ===========================================================================
#define TCG_SMEM_BYTES 132160

template <bool FUSE>
__global__ __launch_bounds__(256, 1) __cluster_dims__(1, 1, 1) void tc_gemm(
    const float* __restrict__ W,
    const float* __restrict__ X1,
    const float* __restrict__ X2,
    float* __restrict__ Out)
{
#if TC_OK
    extern __shared__ uint8_t dsm[];
    const uint32_t raw  = smem_to_u32(dsm);
    const uint32_t base = (raw + 1023u) & ~1023u;
    uint8_t* p = dsm + (base - raw);

    const uint32_t ctrl  = base + 131072;
    const uint32_t mbar0 = ctrl + 8;
    const uint32_t mbar1 = ctrl + 16;

    const int b    = blockIdx.z;
    const int row0 = blockIdx.y * 128;
    const int col0 = blockIdx.x * 128;
    const int tid  = threadIdx.x;
    const int wid  = tid >> 5;
    const int lid  = tid & 31;

    if (wid == 0) TCGEN05_ALLOC(ctrl, 512);
    if (tid == 0) { MBARRIER_INIT(mbar0, 1); MBARRIER_INIT(mbar1, 1); }
    __syncthreads();
    uint32_t tmem;
    asm volatile("ld.shared.b32 %0, [%1];" : "=r"(tmem) : "r"(ctrl));

    const float* Wb  = W + (size_t)row0 * U_;
    const float* X1b = X1 + (size_t)b * U_ * L_ + col0;
    const float* X2b = FUSE ? (X2 + (size_t)b * U_ * L_ + col0) : nullptr;

    auto stage = [&](int c) {
        const int k0 = c * 64;
        uint8_t* bp = p + (c & 1) * 65536;
#pragma unroll
        for (int t = 0; t < 8; t++) {
            int idx = tid + t * 256;
            int m  = idx >> 4;
            int k4 = (idx & 15) << 2;
            float4 v = *(const float4*)(Wb + (size_t)m * U_ + k0 + k4);
            uint16_t h0, l0, h1, l1, h2, l2, h3, l3;
            bf16_split(v.x, h0, l0); bf16_split(v.y, h1, l1);
            bf16_split(v.z, h2, l2); bf16_split(v.w, h3, l3);
            uint2 hv = make_uint2((uint32_t)h0 | ((uint32_t)h1 << 16),
                                  (uint32_t)h2 | ((uint32_t)h3 << 16));
            uint2 lv = make_uint2((uint32_t)l0 | ((uint32_t)l1 << 16),
                                  (uint32_t)l2 | ((uint32_t)l3 << 16));
            uint32_t off = (uint32_t)((m >> 3) * 1024 + (m & 7) * 128 + k4 * 2);
            uint32_t sw = SW128(off);
            *(uint2*)(bp + sw)         = hv;
            *(uint2*)(bp + 16384 + sw) = lv;
        }
        {
            float r[8][4];
#pragma unroll
            for (int kk = 0; kk < 8; kk++) {
                const float* xr = X1b + (size_t)(k0 + wid * 8 + kk) * L_;
                const float* yr = FUSE ? (X2b + (size_t)(k0 + wid * 8 + kk) * L_) : nullptr;
#pragma unroll
                for (int ei = 0; ei < 4; ei++) {
                    int n = lid + 32 * ei;
                    float v = xr[n];
                    if (FUSE) v = 0.5f * (v + yr[n]);
                    r[kk][ei] = v;
                }
            }
#pragma unroll
            for (int ei = 0; ei < 4; ei++) {
                int n = lid + 32 * ei;
                uint16_t h[8], l[8];
#pragma unroll
                for (int kk = 0; kk < 8; kk++) bf16_split(r[kk][ei], h[kk], l[kk]);
                uint4 hv = make_uint4((uint32_t)h[0] | ((uint32_t)h[1] << 16),
                                      (uint32_t)h[2] | ((uint32_t)h[3] << 16),
                                      (uint32_t)h[4] | ((uint32_t)h[5] << 16),
                                      (uint32_t)h[6] | ((uint32_t)h[7] << 16));
                uint4 lv = make_uint4((uint32_t)l[0] | ((uint32_t)l[1] << 16),
                                      (uint32_t)l[2] | ((uint32_t)l[3] << 16),
                                      (uint32_t)l[4] | ((uint32_t)l[5] << 16),
                                      (uint32_t)l[6] | ((uint32_t)l[7] << 16));
                uint32_t off = (uint32_t)((n >> 3) * 1024 + (n & 7) * 128 + wid * 16);
                uint32_t sw = SW128(off);
                *(uint4*)(bp + 32768 + sw) = hv;
                *(uint4*)(bp + 49152 + sw) = lv;
            }
        }
        FENCE_PROXY_ASYNC_SHARED_CTA();
    };

    stage(0);
    __syncthreads();

    const int NC = U_ / 64;   // 8 chunks
    for (int c = 0; c < NC; c++) {
        if (wid == 0 && elect_one_pred()) {
            uint32_t bb = base + (uint32_t)(c & 1) * 65536u;
            uint64_t ahi = desc_k_major(bb);
            uint64_t alo = desc_k_major(bb + 16384);
            uint64_t bhi = desc_k_major(bb + 32768);
            uint64_t blo = desc_k_major(bb + 49152);
#pragma unroll
            for (int s = 0; s < 4; s++) {
                uint64_t so = (uint64_t)(s * 2);
                mma_f16_ss(tmem, ahi + so, bhi + so, IDESC_BF16_N128,
                           (c == 0 && s == 0) ? 0u : 1u);
                mma_f16_ss(tmem, ahi + so, blo + so, IDESC_BF16_N128, 1u);
                mma_f16_ss(tmem, alo + so, bhi + so, IDESC_BF16_N128, 1u);
            }
            TCGEN05_COMMIT((c & 1) ? mbar1 : mbar0);
        }
        if (c + 1 < NC) {
            if (c >= 1) {
                // buffer (c+1)&1 was last consumed by MMA chunk c-1;
                // that chunk is completion #(((c+1)>>1)-1) on mbar[(c+1)&1]
                uint32_t mb = ((c + 1) & 1) ? mbar1 : mbar0;
                MBARRIER_WAIT_PARITY(mb, (((c + 1) >> 1) - 1) & 1);
            }
            stage(c + 1);
            __syncthreads();
        }
    }

    // chunk 7 is completion #3 on mbar1 -> parity 1
    MBARRIER_WAIT_PARITY(mbar1, 1);
    TCGEN05_FENCE_AFTER();

    if (wid < 4) {
        const int m = wid * 32 + lid;
        float* op = Out + ((size_t)b * U_ + row0 + m) * L_ + col0;
#pragma unroll
        for (int j = 0; j < 4; j++) {
            uint32_t r32[32];
            TCGEN05_LD_32X32B_X32(r32, tmem + j * 32);
            TCGEN05_WAIT_LD();
            TCGEN05_FENCE_BEFORE();
#pragma unroll
            for (int q = 0; q < 8; q++) {
                float4 v = make_float4(__uint_as_float(r32[q * 4 + 0]),
                                       __uint_as_float(r32[q * 4 + 1]),
                                       __uint_as_float(r32[q * 4 + 2]),
                                       __uint_as_float(r32[q * 4 + 3]));
                *(float4*)(op + j * 32 + q * 4) = v;
            }
        }
    }
    __syncthreads();
    if (wid == 0) TCGEN05_DEALLOC(tmem, 512);
#else
    (void)W; (void)X1; (void)X2; (void)Out;
#endif
}

// ===========================================================================
// tcgen05 attention — 256 threads; LDTM/convert split across all 8 warps.
// smem: QHI 0 | QLO 16384 | KTHI 32768 | KTLO 40960 | KHI 49152 | KLO 57344
//       SHI 65536 | SLO 81920 | MS 98304 (128x68B, reused as cnt[256] late)
//       ctrl 107008
// ===========================================================================
#define AT_SMEM_BYTES 108576

__global__ __launch_bounds__(256, 1) __cluster_dims__(1, 1, 1) void attn_tc(
    const float* __restrict__ Q, const float* __restrict__ K,
    const int* __restrict__ mask, float* __restrict__ C)
{
#if TC_OK
    extern __shared__ uint8_t dsm[];
    const uint32_t raw  = smem_to_u32(dsm);
    const uint32_t base = (raw + 1023u) & ~1023u;
    uint8_t* p = dsm + (base - raw);

    const uint32_t QHI = base, QLO = base + 16384;
    const uint32_t KTHI = base + 32768, KTLO = base + 40960;
    const uint32_t KHI = base + 49152, KLO = base + 57344;
    const uint32_t SHI = base + 65536, SLO = base + 81920;
    uint8_t* Msp = p + 98304;
    const uint32_t ctrl = base + 107008;
    const uint32_t mbar = ctrl + 8;

    const int b  = blockIdx.z;
    const int h  = blockIdx.x;
    const int x0 = blockIdx.y * 128;
    const int tid = threadIdx.x;
    const int wid = tid >> 5;
    const int lid = tid & 31;
    const int sub  = wid & 3;    // TMEM subpartition (row group)
    const int half = wid >> 2;   // column half for LDTM split

    if (wid == 0) TCGEN05_ALLOC(ctrl, 512);
    if (tid == 0) MBARRIER_INIT(mbar, 1);
    __syncthreads();
    uint32_t tmem;
    asm volatile("ld.shared.b32 %0, [%1];" : "=r"(tmem) : "r"(ctrl));

    const float* Qb = Q + ((size_t)(b * U_ + h * D_)) * L_ + x0;
    const float* Kb = K + ((size_t)(b * U_ + h * D_)) * L_;
    const int*   Mb = mask + ((size_t)b * L_ + x0) * L_;

    // ---- stage Q^T [128x][64d] hi/lo (scale folded); warp owns 8 d-cols ----
    {
        float r[8][4];
#pragma unroll
        for (int kk = 0; kk < 8; kk++) {
            const float* qr = Qb + (size_t)(wid * 8 + kk) * L_;
#pragma unroll
            for (int ei = 0; ei < 4; ei++)
                r[kk][ei] = qr[lid + 32 * ei] * SCALE_;
        }
#pragma unroll
        for (int ei = 0; ei < 4; ei++) {
            int x = lid + 32 * ei;
            uint16_t hh[8], ll[8];
#pragma unroll
            for (int kk = 0; kk < 8; kk++) bf16_split(r[kk][ei], hh[kk], ll[kk]);
            uint4 hv = make_uint4((uint32_t)hh[0] | ((uint32_t)hh[1] << 16),
                                  (uint32_t)hh[2] | ((uint32_t)hh[3] << 16),
                                  (uint32_t)hh[4] | ((uint32_t)hh[5] << 16),
                                  (uint32_t)hh[6] | ((uint32_t)hh[7] << 16));
            uint4 lv = make_uint4((uint32_t)ll[0] | ((uint32_t)ll[1] << 16),
                                  (uint32_t)ll[2] | ((uint32_t)ll[3] << 16),
                                  (uint32_t)ll[4] | ((uint32_t)ll[5] << 16),
                                  (uint32_t)ll[6] | ((uint32_t)ll[7] << 16));
            uint32_t sw = SW128((uint32_t)((x >> 3) * 1024 + (x & 7) * 128 + wid * 16));
            *(uint4*)(p + (QHI - base) + sw) = hv;
            *(uint4*)(p + (QLO - base) + sw) = lv;
        }
    }

    int cnt = 0;          // per-lane mask count: row x = sub*32+lid, cols half*32..+31
    int ph = 0;

    for (int yt = 0; yt < 16; yt++) {
        const int y0 = yt * 64;

        // ---- stage K^T [64y][64d]; warp owns 8 d-cols ----
        {
            float r[8][2];
#pragma unroll
            for (int kk = 0; kk < 8; kk++) {
                const float* kr = Kb + (size_t)(wid * 8 + kk) * L_ + y0;
#pragma unroll
                for (int ei = 0; ei < 2; ei++)
                    r[kk][ei] = kr[lid + 32 * ei];
            }
#pragma unroll
            for (int ei = 0; ei < 2; ei++) {
                int y = lid + 32 * ei;
                uint16_t hh[8], ll[8];
#pragma unroll
                for (int kk = 0; kk < 8; kk++) bf16_split(r[kk][ei], hh[kk], ll[kk]);
                uint4 hv = make_uint4((uint32_t)hh[0] | ((uint32_t)hh[1] << 16),
                                      (uint32_t)hh[2] | ((uint32_t)hh[3] << 16),
                                      (uint32_t)hh[4] | ((uint32_t)hh[5] << 16),
                                      (uint32_t)hh[6] | ((uint32_t)hh[7] << 16));
                uint4 lv = make_uint4((uint32_t)ll[0] | ((uint32_t)ll[1] << 16),
                                      (uint32_t)ll[2] | ((uint32_t)ll[3] << 16),
                                      (uint32_t)ll[4] | ((uint32_t)ll[5] << 16),
                                      (uint32_t)ll[6] | ((uint32_t)ll[7] << 16));
                uint32_t sw = SW128((uint32_t)((y >> 3) * 1024 + (y & 7) * 128 + wid * 16));
                *(uint4*)(p + (KTHI - base) + sw) = hv;
                *(uint4*)(p + (KTLO - base) + sw) = lv;
            }
        }
        // ---- stage K [64d][64y] (natural) ----
#pragma unroll
        for (int t = 0; t < 4; t++) {
            int idx = tid + t * 256;
            int d  = idx >> 4;
            int y4 = (idx & 15) << 2;
            float4 v = *(const float4*)(Kb + (size_t)d * L_ + y0 + y4);
            uint16_t h0, l0, h1, l1, h2, l2, h3, l3;
            bf16_split(v.x, h0, l0); bf16_split(v.y, h1, l1);
            bf16_split(v.z, h2, l2); bf16_split(v.w, h3, l3);
            uint2 hv = make_uint2((uint32_t)h0 | ((uint32_t)h1 << 16),
                                  (uint32_t)h2 | ((uint32_t)h3 << 16));
            uint2 lv = make_uint2((uint32_t)l0 | ((uint32_t)l1 << 16),
                                  (uint32_t)l2 | ((uint32_t)l3 << 16));
            uint32_t sw = SW128((uint32_t)((d >> 3) * 1024 + (d & 7) * 128 + y4 * 2));
            *(uint2*)(p + (KHI - base) + sw) = hv;
            *(uint2*)(p + (KLO - base) + sw) = lv;
        }
        // ---- stage mask tile ----
#pragma unroll
        for (int t = 0; t < 8; t++) {
            int idx = tid + t * 256;
            int xr = idx >> 4;
            int yw = idx & 15;
            int4 m = *(const int4*)(Mb + (size_t)xr * L_ + y0 + yw * 4);
            uint32_t packed = (m.x != 0 ? 1u : 0u)
                            | (m.y != 0 ? 1u << 8 : 0u)
                            | (m.z != 0 ? 1u << 16 : 0u)
                            | (m.w != 0 ? 1u << 24 : 0u);
            *(uint32_t*)(Msp + xr * 68 + yw * 4) = packed;
        }
        FENCE_PROXY_ASYNC_SHARED_CTA();
        __syncthreads();

        // ---- MMA1: S = Q^T K ----
        if (wid == 0 && elect_one_pred()) {
            uint64_t ah = desc_k_major(QHI), al = desc_k_major(QLO);
            uint64_t bh = desc_k_major(KTHI), bl = desc_k_major(KTLO);
#pragma unroll
            for (int s = 0; s < 4; s++) {
                uint64_t so = (uint64_t)(s * 2);
                mma_f16_ss(tmem, ah + so, bh + so, IDESC_BF16_N64, s > 0 ? 1u : 0u);
                mma_f16_ss(tmem, ah + so, bl + so, IDESC_BF16_N64, 1u);
                mma_f16_ss(tmem, al + so, bh + so, IDESC_BF16_N64, 1u);
            }
            TCGEN05_COMMIT(mbar);
        }
        MBARRIER_WAIT_PARITY(mbar, ph & 1); ph++;
        TCGEN05_FENCE_AFTER();

        // ---- LDTM S (cols half*32..+31), relu+mask+count, stage S' ----
        {
            uint32_t s0[32];
            TCGEN05_LD_32X32B_X32(s0, tmem + half * 32);
            TCGEN05_WAIT_LD();
            TCGEN05_FENCE_BEFORE();
            const int x = sub * 32 + lid;
            uint32_t mw[8];
#pragma unroll
            for (int i = 0; i < 8; i++)
                mw[i] = *(uint32_t*)(Msp + x * 68 + half * 32 + i * 4);
            uint16_t hh[32], ll[32];
#pragma unroll
            for (int j = 0; j < 32; j++) {
                float v = __uint_as_float(s0[j]);
                v = v > 0.f ? v : 0.f;
                uint32_t mb = (mw[j >> 2] >> ((j & 3) * 8)) & 0xFFu;
                v = mb ? v : 0.f;
                cnt += mb ? 1 : 0;
                bf16_split(v, hh[j], ll[j]);
            }
            uint32_t off = (uint32_t)((x >> 3) * 1024 + (x & 7) * 128 + half * 64);
#pragma unroll
            for (int g = 0; g < 4; g++) {
                uint4 hv = make_uint4(
                    (uint32_t)hh[g*8+0] | ((uint32_t)hh[g*8+1] << 16),
                    (uint32_t)hh[g*8+2] | ((uint32_t)hh[g*8+3] << 16),
                    (uint32_t)hh[g*8+4] | ((uint32_t)hh[g*8+5] << 16),
                    (uint32_t)hh[g*8+6] | ((uint32_t)hh[g*8+7] << 16));
                uint4 lv = make_uint4(
                    (uint32_t)ll[g*8+0] | ((uint32_t)ll[g*8+1] << 16),
                    (uint32_t)ll[g*8+2] | ((uint32_t)ll[g*8+3] << 16),
                    (uint32_t)ll[g*8+4] | ((uint32_t)ll[g*8+5] << 16),
                    (uint32_t)ll[g*8+6] | ((uint32_t)ll[g*8+7] << 16));
                uint32_t sw = SW128(off + g * 16);
                *(uint4*)(p + (SHI - base) + sw) = hv;
                *(uint4*)(p + (SLO - base) + sw) = lv;
            }
        }
        FENCE_PROXY_ASYNC_SHARED_CTA();
        __syncthreads();

        // ---- MMA2: C^T[x,d] += S' K ----
        if (wid == 0 && elect_one_pred()) {
            uint64_t ah = desc_k_major(SHI), al = desc_k_major(SLO);
            uint64_t bh = desc_k_major(KHI), bl = desc_k_major(KLO);
#pragma unroll
            for (int s = 0; s < 4; s++) {
                uint64_t so = (uint64_t)(s * 2);
                mma_f16_ss(tmem + 64, ah + so, bh + so, IDESC_BF16_N64,
                           (yt == 0 && s == 0) ? 0u : 1u);
                mma_f16_ss(tmem + 64, ah + so, bl + so, IDESC_BF16_N64, 1u);
                mma_f16_ss(tmem + 64, al + so, bh + so, IDESC_BF16_N64, 1u);
            }
            TCGEN05_COMMIT(mbar);
        }
        MBARRIER_WAIT_PARITY(mbar, ph & 1); ph++;
    }

    TCGEN05_FENCE_AFTER();

    // ---- epilogue: combine counts, normalize, transpose via d-major scr ----
    {
        uint32_t c0[32];
        TCGEN05_LD_32X32B_X32(c0, tmem + 64 + half * 32);
        TCGEN05_WAIT_LD();
        TCGEN05_FENCE_BEFORE();
        const int x = sub * 32 + lid;
        int* cnts = (int*)Msp;           // reuse mask region (loop done)
        float* scr = (float*)p;          // reuse Q/KT region, d-major [64][132]
        __syncthreads();                 // everyone past loop smem use
        cnts[half * 128 + x] = cnt;
        __syncthreads();
        int tot = cnts[x] + cnts[128 + x];
        float inv = 1.0f / (float)(tot > 0 ? tot : 1);
#pragma unroll
        for (int j = 0; j < 32; j++) {
            float v = __uint_as_float(c0[j]) * inv;
            scr[(half * 32 + j) * 132 + x] = v;   // conflict-free (x contiguous)
        }
        __syncthreads();
        float* Cb = C + ((size_t)(b * U_ + h * D_)) * L_ + x0;
#pragma unroll
        for (int t = 0; t < 8; t++) {
            int idx = tid + t * 256;
            int d  = idx >> 5;
            int x4 = (idx & 31) << 2;
            float4 v = *(float4*)&scr[d * 132 + x4];  // conflict-free LDS.128
            *(float4*)(Cb + (size_t)d * L_ + x4) = v;
        }
    }
    __syncthreads();
    if (wid == 0) TCGEN05_DEALLOC(tmem, 512);
#else
    (void)Q; (void)K; (void)mask; (void)C;
#endif
}

// ---------------------------------------------------------------------------
extern "C" void kernel_launch(void* const* d_in, const int* in_sizes, int n_in,
                              void* d_out, int out_size)
{
    const float* x  = (const float*)d_in[0];
    const float* y  = (const float*)d_in[1];
    const int*   mk = (const int*)d_in[2];
    const float* wq = (const float*)d_in[3];
    const float* wk = (const float*)d_in[4];
    const float* wo = (const float*)d_in[5];
    float* out = (float*)d_out;

    float *Qp, *Kp, *Cp;
    cudaGetSymbolAddress((void**)&Qp, g_Q);
    cudaGetSymbolAddress((void**)&Kp, g_K);
    cudaGetSymbolAddress((void**)&Cp, g_C);

    cudaFuncSetAttribute(tc_gemm<false>, cudaFuncAttributeMaxDynamicSharedMemorySize,
                         TCG_SMEM_BYTES);
    cudaFuncSetAttribute(tc_gemm<true>, cudaFuncAttributeMaxDynamicSharedMemorySize,
                         TCG_SMEM_BYTES);
    cudaFuncSetAttribute(attn_tc, cudaFuncAttributeMaxDynamicSharedMemorySize,
                         AT_SMEM_BYTES);

    dim3 gg(L_ / 128, U_ / 128, B_);   // (8, 4, 16)
    tc_gemm<false><<<gg, 256, TCG_SMEM_BYTES>>>(wq, x, nullptr, Qp);
    tc_gemm<false><<<gg, 256, TCG_SMEM_BYTES>>>(wk, y, nullptr, Kp);
    attn_tc<<<dim3(H_, L_ / 128, B_), 256, AT_SMEM_BYTES>>>(Qp, Kp, mk, Cp);
    tc_gemm<true><<<gg, 256, TCG_SMEM_BYTES>>>(wo, Qp, Cp, out);
}

// round 11
// speedup vs baseline: 2.4608x; 1.0541x over previous
#include <cuda_runtime.h>
#include <cuda_bf16.h>
#include <cstdint>
#include <cstddef>

// Problem constants
#define B_  16
#define U_  512
#define L_  1024
#define H_  8
#define D_  64
#define SCALE_ 0.125f   // 1/sqrt(64)

// Scratch (device globals — allocation-free rule).
__device__ __align__(256) float g_Q[(size_t)B_ * U_ * L_];
__device__ __align__(256) float g_K[(size_t)B_ * U_ * L_];
__device__ __align__(256) float g_C[(size_t)B_ * U_ * L_];

// ===========================================================================
// Arch gating
// ===========================================================================
#if defined(__CUDA_ARCH_FEAT_SM103_ALL) || defined(__CUDA_ARCH_FEAT_SM100_ALL) || \
    defined(__CUDA_ARCH_FAMILY_SPECIFIC__) || defined(__CUDA_ARCH_SPECIFIC__)
#define TC_OK 1
#else
#define TC_OK 0
#endif

__device__ __forceinline__ uint32_t smem_to_u32(const void* p) {
    uint32_t a;
    asm("{ .reg .u64 t; cvta.to.shared.u64 t, %1; cvt.u32.u64 %0, t; }" : "=r"(a) : "l"(p));
    return a;
}
#define MBARRIER_INIT(mbar, count) \
    asm volatile("mbarrier.init.shared.b64 [%0], %1;" \
                 :: "r"((uint32_t)(mbar)), "r"((uint32_t)(count)) : "memory")
#define MBARRIER_WAIT_PARITY(mbar, parity) do {                                   \
    uint32_t _m = (uint32_t)(mbar); uint32_t _p = (uint32_t)(parity);             \
    asm volatile("{\n\t.reg .pred P1;\n\t"                                        \
        "WAIT_LOOP_%=:\n\t"                                                        \
        "mbarrier.try_wait.parity.acquire.cta.shared::cta.b64 P1, [%0], %1, 0x989680;\n\t" \
        "@P1 bra.uni WAIT_DONE_%=;\n\t"                                            \
        "bra.uni WAIT_LOOP_%=;\n\t"                                                \
        "WAIT_DONE_%=:\n\t}" :: "r"(_m), "r"(_p) : "memory");                      \
} while (0)
#define FENCE_PROXY_ASYNC_SHARED_CTA() asm volatile("fence.proxy.async.shared::cta;" ::: "memory")

#if TC_OK
__device__ __forceinline__ uint32_t elect_one_pred() {
    uint32_t pred;
    asm volatile("{\n\t.reg .pred p;\n\telect.sync _|p, 0xFFFFFFFF;\n\tselp.b32 %0, 1, 0, p;\n\t}"
                 : "=r"(pred));
    return pred;
}
#define TCGEN05_ALLOC(smem_result_addr, nCols) \
    asm volatile("tcgen05.alloc.cta_group::1.sync.aligned.shared::cta.b32 [%0], %1;" \
                 :: "r"((uint32_t)(smem_result_addr)), "r"((uint32_t)(nCols)) : "memory")
#define TCGEN05_DEALLOC(tmem_addr, nCols) \
    asm volatile("tcgen05.dealloc.cta_group::1.sync.aligned.b32 %0, %1;" \
                 :: "r"(tmem_addr), "r"((uint32_t)(nCols)))
#define TCGEN05_RELINQUISH() \
    asm volatile("tcgen05.relinquish_alloc_permit.cta_group::1.sync.aligned;")
#define TCGEN05_COMMIT(mbar) \
    asm volatile("tcgen05.commit.cta_group::1.mbarrier::arrive::one.shared::cluster.b64 [%0];" \
                 :: "r"((uint32_t)(mbar)) : "memory")
#define TCGEN05_FENCE_BEFORE() asm volatile("tcgen05.fence::before_thread_sync;" ::: "memory")
#define TCGEN05_FENCE_AFTER()  asm volatile("tcgen05.fence::after_thread_sync;"  ::: "memory")
#define TCGEN05_WAIT_LD()      asm volatile("tcgen05.wait::ld.sync.aligned;"     ::: "memory")
#define TCGEN05_LD_32X32B_X32(r, tmem_addr) \
    asm volatile( \
        "tcgen05.ld.sync.aligned.32x32b.x32.b32 " \
        "{%0, %1, %2, %3, %4, %5, %6, %7, " \
        " %8, %9, %10, %11, %12, %13, %14, %15, " \
        " %16, %17, %18, %19, %20, %21, %22, %23, " \
        " %24, %25, %26, %27, %28, %29, %30, %31}, [%32];" \
        : "=r"((r)[0]),  "=r"((r)[1]),  "=r"((r)[2]),  "=r"((r)[3]), \
          "=r"((r)[4]),  "=r"((r)[5]),  "=r"((r)[6]),  "=r"((r)[7]), \
          "=r"((r)[8]),  "=r"((r)[9]),  "=r"((r)[10]), "=r"((r)[11]), \
          "=r"((r)[12]), "=r"((r)[13]), "=r"((r)[14]), "=r"((r)[15]), \
          "=r"((r)[16]), "=r"((r)[17]), "=r"((r)[18]), "=r"((r)[19]), \
          "=r"((r)[20]), "=r"((r)[21]), "=r"((r)[22]), "=r"((r)[23]), \
          "=r"((r)[24]), "=r"((r)[25]), "=r"((r)[26]), "=r"((r)[27]), \
          "=r"((r)[28]), "=r"((r)[29]), "=r"((r)[30]), "=r"((r)[31]) \
        : "r"(tmem_addr))
#define TCGEN05_LD_32X32B_X16(r, tmem_addr) \
    asm volatile( \
        "tcgen05.ld.sync.aligned.32x32b.x16.b32 " \
        "{%0, %1, %2, %3, %4, %5, %6, %7, " \
        " %8, %9, %10, %11, %12, %13, %14, %15}, [%16];" \
        : "=r"((r)[0]),  "=r"((r)[1]),  "=r"((r)[2]),  "=r"((r)[3]), \
          "=r"((r)[4]),  "=r"((r)[5]),  "=r"((r)[6]),  "=r"((r)[7]), \
          "=r"((r)[8]),  "=r"((r)[9]),  "=r"((r)[10]), "=r"((r)[11]), \
          "=r"((r)[12]), "=r"((r)[13]), "=r"((r)[14]), "=r"((r)[15]) \
        : "r"(tmem_addr))

__device__ __forceinline__ void mma_f16_ss(uint32_t d_tmem, uint64_t a_desc,
                                           uint64_t b_desc, uint32_t idesc,
                                           uint32_t enable) {
    asm volatile(
        "{\n\t"
        ".reg .pred p;\n\t"
        "setp.ne.u32 p, %5, 0;\n\t"
        "tcgen05.mma.cta_group::1.kind::f16 [%0], %1, %2, %3, {%4, %4, %4, %4}, p;\n\t"
        "}"
        :: "r"(d_tmem), "l"(a_desc), "l"(b_desc), "r"(idesc), "r"(0u), "r"(enable)
        : "memory");
}
#endif  // TC_OK

// K-major SW128 descriptor
__device__ __forceinline__ uint64_t desc_k_major(uint32_t addr) {
    return ((uint64_t)(addr >> 4) & 0x3FFF)
         | (1ull << 16) | (64ull << 32) | (1ull << 46) | (2ull << 61);
}

#define SW128(off) ((off) ^ (((off) >> 3) & 0x70))

#define IDESC_BF16_N128 0x8200490u
#define IDESC_BF16_N64  0x8100490u

__device__ __forceinline__ void bf16_split(float x, uint16_t& hi, uint16_t& lo) {
    __nv_bfloat16 h = __float2bfloat16(x);
    float r = x - __bfloat162float(h);
    __nv_bfloat16 l = __float2bfloat16(r);
    hi = __bfloat16_as_ushort(h);
    lo = __bfloat16_as_ushort(l);
}

// ===========================================================================
// tcgen05 split-bf16 channel-mix GEMM — serialized, single buffer, 2 CTAs/SM.
//   buffer: Ahi 0 | Alo 16384 | Bhi 32768 | Blo 49152 | ctrl 65536
// ===========================================================================
#define TCG_SMEM_BYTES 66688

template <bool FUSE>
__global__ __launch_bounds__(256, 2) __cluster_dims__(1, 1, 1) void tc_gemm(
    const float* __restrict__ W,
    const float* __restrict__ X1,
    const float* __restrict__ X2,
    float* __restrict__ Out)
{
#if TC_OK
    extern __shared__ uint8_t dsm[];
    const uint32_t raw  = smem_to_u32(dsm);
    const uint32_t base = (raw + 1023u) & ~1023u;
    uint8_t* p = dsm + (base - raw);

    const uint32_t ctrl = base + 65536;
    const uint32_t mbar = ctrl + 8;

    const int b    = blockIdx.z;
    const int row0 = blockIdx.y * 128;
    const int col0 = blockIdx.x * 128;
    const int tid  = threadIdx.x;
    const int wid  = tid >> 5;
    const int lid  = tid & 31;

    if (wid == 0) {
        TCGEN05_ALLOC(ctrl, 256);
        TCGEN05_RELINQUISH();   // free the permit for the co-resident CTA
    }
    if (tid == 0) MBARRIER_INIT(mbar, 1);
    __syncthreads();
    uint32_t tmem;
    asm volatile("ld.shared.b32 %0, [%1];" : "=r"(tmem) : "r"(ctrl));

    const float* Wb  = W + (size_t)row0 * U_;
    const float* X1b = X1 + (size_t)b * U_ * L_ + col0;
    const float* X2b = FUSE ? (X2 + (size_t)b * U_ * L_ + col0) : nullptr;

    const int NC = U_ / 64;   // 8 chunks
    for (int c = 0; c < NC; c++) {
        const int k0 = c * 64;
        // ---- stage A: W[128m x 64k] bf16 hi/lo, K-major SW128 ----
#pragma unroll 2
        for (int t = 0; t < 8; t++) {
            int idx = tid + t * 256;
            int m  = idx >> 4;
            int k4 = (idx & 15) << 2;
            float4 v = *(const float4*)(Wb + (size_t)m * U_ + k0 + k4);
            uint16_t h0, l0, h1, l1, h2, l2, h3, l3;
            bf16_split(v.x, h0, l0); bf16_split(v.y, h1, l1);
            bf16_split(v.z, h2, l2); bf16_split(v.w, h3, l3);
            uint2 hv = make_uint2((uint32_t)h0 | ((uint32_t)h1 << 16),
                                  (uint32_t)h2 | ((uint32_t)h3 << 16));
            uint2 lv = make_uint2((uint32_t)l0 | ((uint32_t)l1 << 16),
                                  (uint32_t)l2 | ((uint32_t)l3 << 16));
            uint32_t off = (uint32_t)((m >> 3) * 1024 + (m & 7) * 128 + k4 * 2);
            uint32_t sw = SW128(off);
            *(uint2*)(p + sw)         = hv;
            *(uint2*)(p + 16384 + sw) = lv;
        }
        // ---- stage B: X[64k x 128n] -> [128n x 64k] bf16 hi/lo (reg-light) ----
#pragma unroll
        for (int ei = 0; ei < 4; ei++) {
            int n = lid + 32 * ei;
            float rv[8];
#pragma unroll
            for (int kk = 0; kk < 8; kk++) {
                size_t ro = (size_t)(k0 + wid * 8 + kk) * L_ + n;
                float v = X1b[ro];
                if (FUSE) v = 0.5f * (v + X2b[ro]);
                rv[kk] = v;
            }
            uint16_t h[8], l[8];
#pragma unroll
            for (int kk = 0; kk < 8; kk++) bf16_split(rv[kk], h[kk], l[kk]);
            uint4 hv = make_uint4((uint32_t)h[0] | ((uint32_t)h[1] << 16),
                                  (uint32_t)h[2] | ((uint32_t)h[3] << 16),
                                  (uint32_t)h[4] | ((uint32_t)h[5] << 16),
                                  (uint32_t)h[6] | ((uint32_t)h[7] << 16));
            uint4 lv = make_uint4((uint32_t)l[0] | ((uint32_t)l[1] << 16),
                                  (uint32_t)l[2] | ((uint32_t)l[3] << 16),
                                  (uint32_t)l[4] | ((uint32_t)l[5] << 16),
                                  (uint32_t)l[6] | ((uint32_t)l[7] << 16));
            uint32_t off = (uint32_t)((n >> 3) * 1024 + (n & 7) * 128 + wid * 16);
            uint32_t sw = SW128(off);
            *(uint4*)(p + 32768 + sw) = hv;
            *(uint4*)(p + 49152 + sw) = lv;
        }
        FENCE_PROXY_ASYNC_SHARED_CTA();
        __syncthreads();

        if (wid == 0 && elect_one_pred()) {
            uint64_t ahi = desc_k_major(base);
            uint64_t alo = desc_k_major(base + 16384);
            uint64_t bhi = desc_k_major(base + 32768);
            uint64_t blo = desc_k_major(base + 49152);
#pragma unroll
            for (int s = 0; s < 4; s++) {
                uint64_t so = (uint64_t)(s * 2);
                mma_f16_ss(tmem, ahi + so, bhi + so, IDESC_BF16_N128,
                           (c == 0 && s == 0) ? 0u : 1u);
                mma_f16_ss(tmem, ahi + so, blo + so, IDESC_BF16_N128, 1u);
                mma_f16_ss(tmem, alo + so, bhi + so, IDESC_BF16_N128, 1u);
            }
            TCGEN05_COMMIT(mbar);
        }
        MBARRIER_WAIT_PARITY(mbar, c & 1);
    }

    TCGEN05_FENCE_AFTER();

    if (wid < 4) {
        const int m = wid * 32 + lid;
        float* op = Out + ((size_t)b * U_ + row0 + m) * L_ + col0;
#pragma unroll
        for (int j = 0; j < 4; j++) {
            uint32_t r32[32];
            TCGEN05_LD_32X32B_X32(r32, tmem + j * 32);
            TCGEN05_WAIT_LD();
            TCGEN05_FENCE_BEFORE();
#pragma unroll
            for (int q = 0; q < 8; q++) {
                float4 v = make_float4(__uint_as_float(r32[q * 4 + 0]),
                                       __uint_as_float(r32[q * 4 + 1]),
                                       __uint_as_float(r32[q * 4 + 2]),
                                       __uint_as_float(r32[q * 4 + 3]));
                *(float4*)(op + j * 32 + q * 4) = v;
            }
        }
    }
    __syncthreads();
    if (wid == 0) TCGEN05_DEALLOC(tmem, 256);
#else
    (void)W; (void)X1; (void)X2; (void)Out;
#endif
}

// ===========================================================================
// tcgen05 attention — 256 threads, 2 CTAs/SM; LDTM in x16 halves (reg-light).
// smem: QHI 0 | QLO 16384 | KTHI 32768 | KTLO 40960 | KHI 49152 | KLO 57344
//       SHI 65536 | SLO 81920 | MS 98304 | ctrl 107008
// ===========================================================================
#define AT_SMEM_BYTES 108576

__global__ __launch_bounds__(256, 2) __cluster_dims__(1, 1, 1) void attn_tc(
    const float* __restrict__ Q, const float* __restrict__ K,
    const int* __restrict__ mask, float* __restrict__ C)
{
#if TC_OK
    extern __shared__ uint8_t dsm[];
    const uint32_t raw  = smem_to_u32(dsm);
    const uint32_t base = (raw + 1023u) & ~1023u;
    uint8_t* p = dsm + (base - raw);

    const uint32_t QHI = base, QLO = base + 16384;
    const uint32_t KTHI = base + 32768, KTLO = base + 40960;
    const uint32_t KHI = base + 49152, KLO = base + 57344;
    const uint32_t SHI = base + 65536, SLO = base + 81920;
    uint8_t* Msp = p + 98304;
    const uint32_t ctrl = base + 107008;
    const uint32_t mbar = ctrl + 8;

    const int b  = blockIdx.z;
    const int h  = blockIdx.x;
    const int x0 = blockIdx.y * 128;
    const int tid = threadIdx.x;
    const int wid = tid >> 5;
    const int lid = tid & 31;
    const int sub  = wid & 3;
    const int half = wid >> 2;

    if (wid == 0) {
        TCGEN05_ALLOC(ctrl, 256);
        TCGEN05_RELINQUISH();
    }
    if (tid == 0) MBARRIER_INIT(mbar, 1);
    __syncthreads();
    uint32_t tmem;
    asm volatile("ld.shared.b32 %0, [%1];" : "=r"(tmem) : "r"(ctrl));

    const float* Qb = Q + ((size_t)(b * U_ + h * D_)) * L_ + x0;
    const float* Kb = K + ((size_t)(b * U_ + h * D_)) * L_;
    const int*   Mb = mask + ((size_t)b * L_ + x0) * L_;

    // ---- stage Q^T [128x][64d] hi/lo (scale folded) ----
#pragma unroll
    for (int ei = 0; ei < 4; ei++) {
        int x = lid + 32 * ei;
        float rv[8];
#pragma unroll
        for (int kk = 0; kk < 8; kk++)
            rv[kk] = Qb[(size_t)(wid * 8 + kk) * L_ + x] * SCALE_;
        uint16_t hh[8], ll[8];
#pragma unroll
        for (int kk = 0; kk < 8; kk++) bf16_split(rv[kk], hh[kk], ll[kk]);
        uint4 hv = make_uint4((uint32_t)hh[0] | ((uint32_t)hh[1] << 16),
                              (uint32_t)hh[2] | ((uint32_t)hh[3] << 16),
                              (uint32_t)hh[4] | ((uint32_t)hh[5] << 16),
                              (uint32_t)hh[6] | ((uint32_t)hh[7] << 16));
        uint4 lv = make_uint4((uint32_t)ll[0] | ((uint32_t)ll[1] << 16),
                              (uint32_t)ll[2] | ((uint32_t)ll[3] << 16),
                              (uint32_t)ll[4] | ((uint32_t)ll[5] << 16),
                              (uint32_t)ll[6] | ((uint32_t)ll[7] << 16));
        uint32_t sw = SW128((uint32_t)((x >> 3) * 1024 + (x & 7) * 128 + wid * 16));
        *(uint4*)(p + (QHI - base) + sw) = hv;
        *(uint4*)(p + (QLO - base) + sw) = lv;
    }

    int cnt = 0;
    int ph = 0;

    for (int yt = 0; yt < 16; yt++) {
        const int y0 = yt * 64;

        // ---- stage K^T [64y][64d] ----
#pragma unroll
        for (int ei = 0; ei < 2; ei++) {
            int y = lid + 32 * ei;
            float rv[8];
#pragma unroll
            for (int kk = 0; kk < 8; kk++)
                rv[kk] = Kb[(size_t)(wid * 8 + kk) * L_ + y0 + y];
            uint16_t hh[8], ll[8];
#pragma unroll
            for (int kk = 0; kk < 8; kk++) bf16_split(rv[kk], hh[kk], ll[kk]);
            uint4 hv = make_uint4((uint32_t)hh[0] | ((uint32_t)hh[1] << 16),
                                  (uint32_t)hh[2] | ((uint32_t)hh[3] << 16),
                                  (uint32_t)hh[4] | ((uint32_t)hh[5] << 16),
                                  (uint32_t)hh[6] | ((uint32_t)hh[7] << 16));
            uint4 lv = make_uint4((uint32_t)ll[0] | ((uint32_t)ll[1] << 16),
                                  (uint32_t)ll[2] | ((uint32_t)ll[3] << 16),
                                  (uint32_t)ll[4] | ((uint32_t)ll[5] << 16),
                                  (uint32_t)ll[6] | ((uint32_t)ll[7] << 16));
            uint32_t sw = SW128((uint32_t)((y >> 3) * 1024 + (y & 7) * 128 + wid * 16));
            *(uint4*)(p + (KTHI - base) + sw) = hv;
            *(uint4*)(p + (KTLO - base) + sw) = lv;
        }
        // ---- stage K [64d][64y] (natural) ----
#pragma unroll 2
        for (int t = 0; t < 4; t++) {
            int idx = tid + t * 256;
            int d  = idx >> 4;
            int y4 = (idx & 15) << 2;
            float4 v = *(const float4*)(Kb + (size_t)d * L_ + y0 + y4);
            uint16_t h0, l0, h1, l1, h2, l2, h3, l3;
            bf16_split(v.x, h0, l0); bf16_split(v.y, h1, l1);
            bf16_split(v.z, h2, l2); bf16_split(v.w, h3, l3);
            uint2 hv = make_uint2((uint32_t)h0 | ((uint32_t)h1 << 16),
                                  (uint32_t)h2 | ((uint32_t)h3 << 16));
            uint2 lv = make_uint2((uint32_t)l0 | ((uint32_t)l1 << 16),
                                  (uint32_t)l2 | ((uint32_t)l3 << 16));
            uint32_t sw = SW128((uint32_t)((d >> 3) * 1024 + (d & 7) * 128 + y4 * 2));
            *(uint2*)(p + (KHI - base) + sw) = hv;
            *(uint2*)(p + (KLO - base) + sw) = lv;
        }
        // ---- stage mask tile ----
#pragma unroll 2
        for (int t = 0; t < 8; t++) {
            int idx = tid + t * 256;
            int xr = idx >> 4;
            int yw = idx & 15;
            int4 m = *(const int4*)(Mb + (size_t)xr * L_ + y0 + yw * 4);
            uint32_t packed = (m.x != 0 ? 1u : 0u)
                            | (m.y != 0 ? 1u << 8 : 0u)
                            | (m.z != 0 ? 1u << 16 : 0u)
                            | (m.w != 0 ? 1u << 24 : 0u);
            *(uint32_t*)(Msp + xr * 68 + yw * 4) = packed;
        }
        FENCE_PROXY_ASYNC_SHARED_CTA();
        __syncthreads();

        // ---- MMA1: S = Q^T K ----
        if (wid == 0 && elect_one_pred()) {
            uint64_t ah = desc_k_major(QHI), al = desc_k_major(QLO);
            uint64_t bh = desc_k_major(KTHI), bl = desc_k_major(KTLO);
#pragma unroll
            for (int s = 0; s < 4; s++) {
                uint64_t so = (uint64_t)(s * 2);
                mma_f16_ss(tmem, ah + so, bh + so, IDESC_BF16_N64, s > 0 ? 1u : 0u);
                mma_f16_ss(tmem, ah + so, bl + so, IDESC_BF16_N64, 1u);
                mma_f16_ss(tmem, al + so, bh + so, IDESC_BF16_N64, 1u);
            }
            TCGEN05_COMMIT(mbar);
        }
        MBARRIER_WAIT_PARITY(mbar, ph & 1); ph++;
        TCGEN05_FENCE_AFTER();

        // ---- LDTM S in x16 halves, relu+mask+count, stage S' ----
        {
            const int x = sub * 32 + lid;
#pragma unroll
            for (int h16 = 0; h16 < 2; h16++) {
                uint32_t s0[16];
                TCGEN05_LD_32X32B_X16(s0, tmem + half * 32 + h16 * 16);
                TCGEN05_WAIT_LD();
                TCGEN05_FENCE_BEFORE();
                uint32_t mw[4];
#pragma unroll
                for (int i = 0; i < 4; i++)
                    mw[i] = *(uint32_t*)(Msp + x * 68 + half * 32 + h16 * 16 + i * 4);
                uint16_t hh[16], ll[16];
#pragma unroll
                for (int j = 0; j < 16; j++) {
                    float v = __uint_as_float(s0[j]);
                    v = v > 0.f ? v : 0.f;
                    uint32_t mb = (mw[j >> 2] >> ((j & 3) * 8)) & 0xFFu;
                    v = mb ? v : 0.f;
                    cnt += mb ? 1 : 0;
                    bf16_split(v, hh[j], ll[j]);
                }
                uint32_t off = (uint32_t)((x >> 3) * 1024 + (x & 7) * 128
                                          + half * 64 + h16 * 32);
#pragma unroll
                for (int g = 0; g < 2; g++) {
                    uint4 hv = make_uint4(
                        (uint32_t)hh[g*8+0] | ((uint32_t)hh[g*8+1] << 16),
                        (uint32_t)hh[g*8+2] | ((uint32_t)hh[g*8+3] << 16),
                        (uint32_t)hh[g*8+4] | ((uint32_t)hh[g*8+5] << 16),
                        (uint32_t)hh[g*8+6] | ((uint32_t)hh[g*8+7] << 16));
                    uint4 lv = make_uint4(
                        (uint32_t)ll[g*8+0] | ((uint32_t)ll[g*8+1] << 16),
                        (uint32_t)ll[g*8+2] | ((uint32_t)ll[g*8+3] << 16),
                        (uint32_t)ll[g*8+4] | ((uint32_t)ll[g*8+5] << 16),
                        (uint32_t)ll[g*8+6] | ((uint32_t)ll[g*8+7] << 16));
                    uint32_t sw = SW128(off + g * 16);
                    *(uint4*)(p + (SHI - base) + sw) = hv;
                    *(uint4*)(p + (SLO - base) + sw) = lv;
                }
            }
        }
        FENCE_PROXY_ASYNC_SHARED_CTA();
        __syncthreads();

        // ---- MMA2: C^T[x,d] += S' K ----
        if (wid == 0 && elect_one_pred()) {
            uint64_t ah = desc_k_major(SHI), al = desc_k_major(SLO);
            uint64_t bh = desc_k_major(KHI), bl = desc_k_major(KLO);
#pragma unroll
            for (int s = 0; s < 4; s++) {
                uint64_t so = (uint64_t)(s * 2);
                mma_f16_ss(tmem + 64, ah + so, bh + so, IDESC_BF16_N64,
                           (yt == 0 && s == 0) ? 0u : 1u);
                mma_f16_ss(tmem + 64, ah + so, bl + so, IDESC_BF16_N64, 1u);
                mma_f16_ss(tmem + 64, al + so, bh + so, IDESC_BF16_N64, 1u);
            }
            TCGEN05_COMMIT(mbar);
        }
        MBARRIER_WAIT_PARITY(mbar, ph & 1); ph++;
    }

    TCGEN05_FENCE_AFTER();

    // ---- epilogue: combine counts, normalize, transpose via d-major scr ----
    {
        const int x = sub * 32 + lid;
        int* cnts = (int*)Msp;
        float* scr = (float*)p;
        __syncthreads();
        cnts[half * 128 + x] = cnt;
        __syncthreads();
        int tot = cnts[x] + cnts[128 + x];
        float inv = 1.0f / (float)(tot > 0 ? tot : 1);
#pragma unroll
        for (int h16 = 0; h16 < 2; h16++) {
            uint32_t c0[16];
            TCGEN05_LD_32X32B_X16(c0, tmem + 64 + half * 32 + h16 * 16);
            TCGEN05_WAIT_LD();
            TCGEN05_FENCE_BEFORE();
#pragma unroll
            for (int j = 0; j < 16; j++) {
                float v = __uint_as_float(c0[j]) * inv;
                scr[(half * 32 + h16 * 16 + j) * 132 + x] = v;
            }
        }
        __syncthreads();
        float* Cb = C + ((size_t)(b * U_ + h * D_)) * L_ + x0;
#pragma unroll 2
        for (int t = 0; t < 8; t++) {
            int idx = tid + t * 256;
            int d  = idx >> 5;
            int x4 = (idx & 31) << 2;
            float4 v = *(float4*)&scr[d * 132 + x4];
            *(float4*)(Cb + (size_t)d * L_ + x4) = v;
        }
    }
    __syncthreads();
    if (wid == 0) TCGEN05_DEALLOC(tmem, 256);
#else
    (void)Q; (void)K; (void)mask; (void)C;
#endif
}

// ---------------------------------------------------------------------------
extern "C" void kernel_launch(void* const* d_in, const int* in_sizes, int n_in,
                              void* d_out, int out_size)
{
    const float* x  = (const float*)d_in[0];
    const float* y  = (const float*)d_in[1];
    const int*   mk = (const int*)d_in[2];
    const float* wq = (const float*)d_in[3];
    const float* wk = (const float*)d_in[4];
    const float* wo = (const float*)d_in[5];
    float* out = (float*)d_out;

    float *Qp, *Kp, *Cp;
    cudaGetSymbolAddress((void**)&Qp, g_Q);
    cudaGetSymbolAddress((void**)&Kp, g_K);
    cudaGetSymbolAddress((void**)&Cp, g_C);

    cudaFuncSetAttribute(tc_gemm<false>, cudaFuncAttributeMaxDynamicSharedMemorySize,
                         TCG_SMEM_BYTES);
    cudaFuncSetAttribute(tc_gemm<true>, cudaFuncAttributeMaxDynamicSharedMemorySize,
                         TCG_SMEM_BYTES);
    cudaFuncSetAttribute(attn_tc, cudaFuncAttributeMaxDynamicSharedMemorySize,
                         AT_SMEM_BYTES);

    dim3 gg(L_ / 128, U_ / 128, B_);   // (8, 4, 16)
    tc_gemm<false><<<gg, 256, TCG_SMEM_BYTES>>>(wq, x, nullptr, Qp);
    tc_gemm<false><<<gg, 256, TCG_SMEM_BYTES>>>(wk, y, nullptr, Kp);
    attn_tc<<<dim3(H_, L_ / 128, B_), 256, AT_SMEM_BYTES>>>(Qp, Kp, mk, Cp);
    tc_gemm<true><<<gg, 256, TCG_SMEM_BYTES>>>(wo, Qp, Cp, out);
}

// round 12
// speedup vs baseline: 3.1961x; 1.2988x over previous
#include <cuda_runtime.h>
#include <cuda_bf16.h>
#include <cstdint>
#include <cstddef>

// Problem constants
#define B_  16
#define U_  512
#define L_  1024
#define H_  8
#define D_  64
#define SCALE_ 0.125f   // 1/sqrt(64)

// Scratch (device globals — allocation-free rule).
__device__ __align__(256) float g_Q[(size_t)B_ * U_ * L_];
__device__ __align__(256) float g_K[(size_t)B_ * U_ * L_];
__device__ __align__(256) float g_C[(size_t)B_ * U_ * L_];

// ===========================================================================
// Arch gating
// ===========================================================================
#if defined(__CUDA_ARCH_FEAT_SM103_ALL) || defined(__CUDA_ARCH_FEAT_SM100_ALL) || \
    defined(__CUDA_ARCH_FAMILY_SPECIFIC__) || defined(__CUDA_ARCH_SPECIFIC__)
#define TC_OK 1
#else
#define TC_OK 0
#endif

__device__ __forceinline__ uint32_t smem_to_u32(const void* p) {
    uint32_t a;
    asm("{ .reg .u64 t; cvta.to.shared.u64 t, %1; cvt.u32.u64 %0, t; }" : "=r"(a) : "l"(p));
    return a;
}
#define MBARRIER_INIT(mbar, count) \
    asm volatile("mbarrier.init.shared.b64 [%0], %1;" \
                 :: "r"((uint32_t)(mbar)), "r"((uint32_t)(count)) : "memory")
#define MBARRIER_WAIT_PARITY(mbar, parity) do {                                   \
    uint32_t _m = (uint32_t)(mbar); uint32_t _p = (uint32_t)(parity);             \
    asm volatile("{\n\t.reg .pred P1;\n\t"                                        \
        "WAIT_LOOP_%=:\n\t"                                                        \
        "mbarrier.try_wait.parity.acquire.cta.shared::cta.b64 P1, [%0], %1, 0x989680;\n\t" \
        "@P1 bra.uni WAIT_DONE_%=;\n\t"                                            \
        "bra.uni WAIT_LOOP_%=;\n\t"                                                \
        "WAIT_DONE_%=:\n\t}" :: "r"(_m), "r"(_p) : "memory");                      \
} while (0)
#define FENCE_PROXY_ASYNC_SHARED_CTA() asm volatile("fence.proxy.async.shared::cta;" ::: "memory")

#if TC_OK
__device__ __forceinline__ uint32_t elect_one_pred() {
    uint32_t pred;
    asm volatile("{\n\t.reg .pred p;\n\telect.sync _|p, 0xFFFFFFFF;\n\tselp.b32 %0, 1, 0, p;\n\t}"
                 : "=r"(pred));
    return pred;
}
#define TCGEN05_ALLOC(smem_result_addr, nCols) \
    asm volatile("tcgen05.alloc.cta_group::1.sync.aligned.shared::cta.b32 [%0], %1;" \
                 :: "r"((uint32_t)(smem_result_addr)), "r"((uint32_t)(nCols)) : "memory")
#define TCGEN05_DEALLOC(tmem_addr, nCols) \
    asm volatile("tcgen05.dealloc.cta_group::1.sync.aligned.b32 %0, %1;" \
                 :: "r"(tmem_addr), "r"((uint32_t)(nCols)))
#define TCGEN05_RELINQUISH() \
    asm volatile("tcgen05.relinquish_alloc_permit.cta_group::1.sync.aligned;")
#define TCGEN05_COMMIT(mbar) \
    asm volatile("tcgen05.commit.cta_group::1.mbarrier::arrive::one.shared::cluster.b64 [%0];" \
                 :: "r"((uint32_t)(mbar)) : "memory")
#define TCGEN05_FENCE_BEFORE() asm volatile("tcgen05.fence::before_thread_sync;" ::: "memory")
#define TCGEN05_FENCE_AFTER()  asm volatile("tcgen05.fence::after_thread_sync;"  ::: "memory")
#define TCGEN05_WAIT_LD()      asm volatile("tcgen05.wait::ld.sync.aligned;"     ::: "memory")
#define TCGEN05_LD_32X32B_X32(r, tmem_addr) \
    asm volatile( \
        "tcgen05.ld.sync.aligned.32x32b.x32.b32 " \
        "{%0, %1, %2, %3, %4, %5, %6, %7, " \
        " %8, %9, %10, %11, %12, %13, %14, %15, " \
        " %16, %17, %18, %19, %20, %21, %22, %23, " \
        " %24, %25, %26, %27, %28, %29, %30, %31}, [%32];" \
        : "=r"((r)[0]),  "=r"((r)[1]),  "=r"((r)[2]),  "=r"((r)[3]), \
          "=r"((r)[4]),  "=r"((r)[5]),  "=r"((r)[6]),  "=r"((r)[7]), \
          "=r"((r)[8]),  "=r"((r)[9]),  "=r"((r)[10]), "=r"((r)[11]), \
          "=r"((r)[12]), "=r"((r)[13]), "=r"((r)[14]), "=r"((r)[15]), \
          "=r"((r)[16]), "=r"((r)[17]), "=r"((r)[18]), "=r"((r)[19]), \
          "=r"((r)[20]), "=r"((r)[21]), "=r"((r)[22]), "=r"((r)[23]), \
          "=r"((r)[24]), "=r"((r)[25]), "=r"((r)[26]), "=r"((r)[27]), \
          "=r"((r)[28]), "=r"((r)[29]), "=r"((r)[30]), "=r"((r)[31]) \
        : "r"(tmem_addr))
#define TCGEN05_LD_32X32B_X16(r, tmem_addr) \
    asm volatile( \
        "tcgen05.ld.sync.aligned.32x32b.x16.b32 " \
        "{%0, %1, %2, %3, %4, %5, %6, %7, " \
        " %8, %9, %10, %11, %12, %13, %14, %15}, [%16];" \
        : "=r"((r)[0]),  "=r"((r)[1]),  "=r"((r)[2]),  "=r"((r)[3]), \
          "=r"((r)[4]),  "=r"((r)[5]),  "=r"((r)[6]),  "=r"((r)[7]), \
          "=r"((r)[8]),  "=r"((r)[9]),  "=r"((r)[10]), "=r"((r)[11]), \
          "=r"((r)[12]), "=r"((r)[13]), "=r"((r)[14]), "=r"((r)[15]) \
        : "r"(tmem_addr))

__device__ __forceinline__ void mma_f16_ss(uint32_t d_tmem, uint64_t a_desc,
                                           uint64_t b_desc, uint32_t idesc,
                                           uint32_t enable) {
    asm volatile(
        "{\n\t"
        ".reg .pred p;\n\t"
        "setp.ne.u32 p, %5, 0;\n\t"
        "tcgen05.mma.cta_group::1.kind::f16 [%0], %1, %2, %3, {%4, %4, %4, %4}, p;\n\t"
        "}"
        :: "r"(d_tmem), "l"(a_desc), "l"(b_desc), "r"(idesc), "r"(0u), "r"(enable)
        : "memory");
}
#endif  // TC_OK

// K-major SW128 descriptor
__device__ __forceinline__ uint64_t desc_k_major(uint32_t addr) {
    return ((uint64_t)(addr >> 4) & 0x3FFF)
         | (1ull << 16) | (64ull << 32) | (1ull << 46) | (2ull << 61);
}

#define SW128(off) ((off) ^ (((off) >> 3) & 0x70))

#define IDESC_BF16_N128 0x8200490u
#define IDESC_BF16_N64  0x8100490u

__device__ __forceinline__ void bf16_split(float x, uint16_t& hi, uint16_t& lo) {
    __nv_bfloat16 h = __float2bfloat16(x);
    float r = x - __bfloat162float(h);
    __nv_bfloat16 l = __float2bfloat16(r);
    hi = __bfloat16_as_ushort(h);
    lo = __bfloat16_as_ushort(l);
}

// ===========================================================================
// tcgen05 split-bf16 channel-mix GEMM — serialized buffer, 2 CTAs/SM,
// global loads for chunk c+1 pipelined across the MMA(c) wait.
// Dispatch: blockIdx.z < B_ -> (Wa, Xa, OutA) else (Wb, Xb, OutB).
//   buffer: Ahi 0 | Alo 16384 | Bhi 32768 | Blo 49152 | ctrl 65536
// ===========================================================================
#define TCG_SMEM_BYTES 66688

template <bool FUSE>
__global__ __launch_bounds__(256, 2) __cluster_dims__(1, 1, 1) void tc_gemm(
    const float* __restrict__ Wa, const float* __restrict__ Xa,
    const float* __restrict__ Wb, const float* __restrict__ Xb,
    const float* __restrict__ X2, float* __restrict__ OutA,
    float* __restrict__ OutB)
{
#if TC_OK
    extern __shared__ uint8_t dsm[];
    const uint32_t raw  = smem_to_u32(dsm);
    const uint32_t base = (raw + 1023u) & ~1023u;
    uint8_t* p = dsm + (base - raw);

    const uint32_t ctrl = base + 65536;
    const uint32_t mbar = ctrl + 8;

    const float* W; const float* X1; float* Out; int b;
    if (blockIdx.z < B_) { W = Wa; X1 = Xa; Out = OutA; b = blockIdx.z; }
    else                 { W = Wb; X1 = Xb; Out = OutB; b = blockIdx.z - B_; }

    const int row0 = blockIdx.y * 128;
    const int col0 = blockIdx.x * 128;
    const int tid  = threadIdx.x;
    const int wid  = tid >> 5;
    const int lid  = tid & 31;

    if (wid == 0) {
        TCGEN05_ALLOC(ctrl, 256);
        TCGEN05_RELINQUISH();
    }
    if (tid == 0) MBARRIER_INIT(mbar, 1);
    __syncthreads();
    uint32_t tmem;
    asm volatile("ld.shared.b32 %0, [%1];" : "=r"(tmem) : "r"(ctrl));

    const float* Wb_  = W + (size_t)row0 * U_;
    const float* X1b = X1 + (size_t)b * U_ * L_ + col0;
    const float* X2b = FUSE ? (X2 + (size_t)b * U_ * L_ + col0) : nullptr;

    float4 aR[8];
    float  bR[4][8];

    auto load_regs = [&](int c) {
        const int k0 = c * 64;
#pragma unroll
        for (int t = 0; t < 8; t++) {
            int idx = tid + t * 256;
            int m  = idx >> 4;
            int k4 = (idx & 15) << 2;
            aR[t] = *(const float4*)(Wb_ + (size_t)m * U_ + k0 + k4);
        }
#pragma unroll
        for (int ei = 0; ei < 4; ei++) {
            int n = lid + 32 * ei;
#pragma unroll
            for (int kk = 0; kk < 8; kk++) {
                size_t ro = (size_t)(k0 + wid * 8 + kk) * L_ + n;
                float v = X1b[ro];
                if (FUSE) v = 0.5f * (v + X2b[ro]);
                bR[ei][kk] = v;
            }
        }
    };

    auto store_stage = [&]() {
#pragma unroll
        for (int t = 0; t < 8; t++) {
            int idx = tid + t * 256;
            int m  = idx >> 4;
            int k4 = (idx & 15) << 2;
            float4 v = aR[t];
            uint16_t h0, l0, h1, l1, h2, l2, h3, l3;
            bf16_split(v.x, h0, l0); bf16_split(v.y, h1, l1);
            bf16_split(v.z, h2, l2); bf16_split(v.w, h3, l3);
            uint2 hv = make_uint2((uint32_t)h0 | ((uint32_t)h1 << 16),
                                  (uint32_t)h2 | ((uint32_t)h3 << 16));
            uint2 lv = make_uint2((uint32_t)l0 | ((uint32_t)l1 << 16),
                                  (uint32_t)l2 | ((uint32_t)l3 << 16));
            uint32_t off = (uint32_t)((m >> 3) * 1024 + (m & 7) * 128 + k4 * 2);
            uint32_t sw = SW128(off);
            *(uint2*)(p + sw)         = hv;
            *(uint2*)(p + 16384 + sw) = lv;
        }
#pragma unroll
        for (int ei = 0; ei < 4; ei++) {
            int n = lid + 32 * ei;
            uint16_t h[8], l[8];
#pragma unroll
            for (int kk = 0; kk < 8; kk++) bf16_split(bR[ei][kk], h[kk], l[kk]);
            uint4 hv = make_uint4((uint32_t)h[0] | ((uint32_t)h[1] << 16),
                                  (uint32_t)h[2] | ((uint32_t)h[3] << 16),
                                  (uint32_t)h[4] | ((uint32_t)h[5] << 16),
                                  (uint32_t)h[6] | ((uint32_t)h[7] << 16));
            uint4 lv = make_uint4((uint32_t)l[0] | ((uint32_t)l[1] << 16),
                                  (uint32_t)l[2] | ((uint32_t)l[3] << 16),
                                  (uint32_t)l[4] | ((uint32_t)l[5] << 16),
                                  (uint32_t)l[6] | ((uint32_t)l[7] << 16));
            uint32_t off = (uint32_t)((n >> 3) * 1024 + (n & 7) * 128 + wid * 16);
            uint32_t sw = SW128(off);
            *(uint4*)(p + 32768 + sw) = hv;
            *(uint4*)(p + 49152 + sw) = lv;
        }
        FENCE_PROXY_ASYNC_SHARED_CTA();
    };

    load_regs(0);
    store_stage();
    __syncthreads();

    const int NC = U_ / 64;   // 8 chunks
    for (int c = 0; c < NC; c++) {
        if (wid == 0 && elect_one_pred()) {
            uint64_t ahi = desc_k_major(base);
            uint64_t alo = desc_k_major(base + 16384);
            uint64_t bhi = desc_k_major(base + 32768);
            uint64_t blo = desc_k_major(base + 49152);
#pragma unroll
            for (int s = 0; s < 4; s++) {
                uint64_t so = (uint64_t)(s * 2);
                mma_f16_ss(tmem, ahi + so, bhi + so, IDESC_BF16_N128,
                           (c == 0 && s == 0) ? 0u : 1u);
                mma_f16_ss(tmem, ahi + so, blo + so, IDESC_BF16_N128, 1u);
                mma_f16_ss(tmem, alo + so, bhi + so, IDESC_BF16_N128, 1u);
            }
            TCGEN05_COMMIT(mbar);
        }
        if (c + 1 < NC) load_regs(c + 1);     // overlaps MMA(c)
        MBARRIER_WAIT_PARITY(mbar, c & 1);
        if (c + 1 < NC) {
            store_stage();
            __syncthreads();
        }
    }

    TCGEN05_FENCE_AFTER();

    if (wid < 4) {
        const int m = wid * 32 + lid;
        float* op = Out + ((size_t)b * U_ + row0 + m) * L_ + col0;
#pragma unroll
        for (int j = 0; j < 4; j++) {
            uint32_t r32[32];
            TCGEN05_LD_32X32B_X32(r32, tmem + j * 32);
            TCGEN05_WAIT_LD();
            TCGEN05_FENCE_BEFORE();
#pragma unroll
            for (int q = 0; q < 8; q++) {
                float4 v = make_float4(__uint_as_float(r32[q * 4 + 0]),
                                       __uint_as_float(r32[q * 4 + 1]),
                                       __uint_as_float(r32[q * 4 + 2]),
                                       __uint_as_float(r32[q * 4 + 3]));
                *(float4*)(op + j * 32 + q * 4) = v;
            }
        }
    }
    __syncthreads();
    if (wid == 0) TCGEN05_DEALLOC(tmem, 256);
#else
    (void)Wa; (void)Xa; (void)Wb; (void)Xb; (void)X2; (void)OutA; (void)OutB;
#endif
}

// ===========================================================================
// tcgen05 attention — 256 threads, 2 CTAs/SM. Mask read from global (L2-hot,
// h fastest grid dim). K-tile global loads for yt+1 pipelined across the
// MMA2(yt) wait.
// smem: QHI 0 | QLO 16384 | KTHI 32768 | KTLO 40960 | KHI 49152 | KLO 57344
//       SHI 65536 | SLO 81920 | ctrl 98304 | cnts 98336
// ===========================================================================
#define AT_SMEM_BYTES 100384

__global__ __launch_bounds__(256, 2) __cluster_dims__(1, 1, 1) void attn_tc(
    const float* __restrict__ Q, const float* __restrict__ K,
    const int* __restrict__ mask, float* __restrict__ C)
{
#if TC_OK
    extern __shared__ uint8_t dsm[];
    const uint32_t raw  = smem_to_u32(dsm);
    const uint32_t base = (raw + 1023u) & ~1023u;
    uint8_t* p = dsm + (base - raw);

    const uint32_t QHI = base, QLO = base + 16384;
    const uint32_t KTHI = base + 32768, KTLO = base + 40960;
    const uint32_t KHI = base + 49152, KLO = base + 57344;
    const uint32_t SHI = base + 65536, SLO = base + 81920;
    const uint32_t ctrl = base + 98304;
    const uint32_t mbar = ctrl + 8;
    int* cnts = (int*)(p + 98336);

    const int b  = blockIdx.z;
    const int h  = blockIdx.x;
    const int x0 = blockIdx.y * 128;
    const int tid = threadIdx.x;
    const int wid = tid >> 5;
    const int lid = tid & 31;
    const int sub  = wid & 3;
    const int half = wid >> 2;

    if (wid == 0) {
        TCGEN05_ALLOC(ctrl, 256);
        TCGEN05_RELINQUISH();
    }
    if (tid == 0) MBARRIER_INIT(mbar, 1);
    __syncthreads();
    uint32_t tmem;
    asm volatile("ld.shared.b32 %0, [%1];" : "=r"(tmem) : "r"(ctrl));

    const float* Qb = Q + ((size_t)(b * U_ + h * D_)) * L_ + x0;
    const float* Kb = K + ((size_t)(b * U_ + h * D_)) * L_;
    const int*   Mb = mask + ((size_t)b * L_ + x0) * L_;

    // ---- stage Q^T [128x][64d] hi/lo (scale folded) ----
#pragma unroll
    for (int ei = 0; ei < 4; ei++) {
        int x = lid + 32 * ei;
        float rv[8];
#pragma unroll
        for (int kk = 0; kk < 8; kk++)
            rv[kk] = Qb[(size_t)(wid * 8 + kk) * L_ + x] * SCALE_;
        uint16_t hh[8], ll[8];
#pragma unroll
        for (int kk = 0; kk < 8; kk++) bf16_split(rv[kk], hh[kk], ll[kk]);
        uint4 hv = make_uint4((uint32_t)hh[0] | ((uint32_t)hh[1] << 16),
                              (uint32_t)hh[2] | ((uint32_t)hh[3] << 16),
                              (uint32_t)hh[4] | ((uint32_t)hh[5] << 16),
                              (uint32_t)hh[6] | ((uint32_t)hh[7] << 16));
        uint4 lv = make_uint4((uint32_t)ll[0] | ((uint32_t)ll[1] << 16),
                              (uint32_t)ll[2] | ((uint32_t)ll[3] << 16),
                              (uint32_t)ll[4] | ((uint32_t)ll[5] << 16),
                              (uint32_t)ll[6] | ((uint32_t)ll[7] << 16));
        uint32_t sw = SW128((uint32_t)((x >> 3) * 1024 + (x & 7) * 128 + wid * 16));
        *(uint4*)(p + (QHI - base) + sw) = hv;
        *(uint4*)(p + (QLO - base) + sw) = lv;
    }

    int cnt = 0;
    int ph = 0;

    // prefetch registers for K tiles
    float  ktR[2][8];   // K^T [64y][64d]: ei x kk
    float4 kR[4];       // K   [64d][64y]: 4 float4 per thread

    auto load_k_regs = [&](int y0n) {
#pragma unroll
        for (int ei = 0; ei < 2; ei++) {
            int y = lid + 32 * ei;
#pragma unroll
            for (int kk = 0; kk < 8; kk++)
                ktR[ei][kk] = Kb[(size_t)(wid * 8 + kk) * L_ + y0n + y];
        }
#pragma unroll
        for (int t = 0; t < 4; t++) {
            int idx = tid + t * 256;
            int d  = idx >> 4;
            int y4 = (idx & 15) << 2;
            kR[t] = *(const float4*)(Kb + (size_t)d * L_ + y0n + y4);
        }
    };

    load_k_regs(0);

    for (int yt = 0; yt < 16; yt++) {
        // ---- store KT from regs ----
#pragma unroll
        for (int ei = 0; ei < 2; ei++) {
            int y = lid + 32 * ei;
            uint16_t hh[8], ll[8];
#pragma unroll
            for (int kk = 0; kk < 8; kk++) bf16_split(ktR[ei][kk], hh[kk], ll[kk]);
            uint4 hv = make_uint4((uint32_t)hh[0] | ((uint32_t)hh[1] << 16),
                                  (uint32_t)hh[2] | ((uint32_t)hh[3] << 16),
                                  (uint32_t)hh[4] | ((uint32_t)hh[5] << 16),
                                  (uint32_t)hh[6] | ((uint32_t)hh[7] << 16));
            uint4 lv = make_uint4((uint32_t)ll[0] | ((uint32_t)ll[1] << 16),
                                  (uint32_t)ll[2] | ((uint32_t)ll[3] << 16),
                                  (uint32_t)ll[4] | ((uint32_t)ll[5] << 16),
                                  (uint32_t)ll[6] | ((uint32_t)ll[7] << 16));
            uint32_t sw = SW128((uint32_t)((y >> 3) * 1024 + (y & 7) * 128 + wid * 16));
            *(uint4*)(p + (KTHI - base) + sw) = hv;
            *(uint4*)(p + (KTLO - base) + sw) = lv;
        }
        // ---- store K from regs ----
#pragma unroll
        for (int t = 0; t < 4; t++) {
            int idx = tid + t * 256;
            int d  = idx >> 4;
            int y4 = (idx & 15) << 2;
            float4 v = kR[t];
            uint16_t h0, l0, h1, l1, h2, l2, h3, l3;
            bf16_split(v.x, h0, l0); bf16_split(v.y, h1, l1);
            bf16_split(v.z, h2, l2); bf16_split(v.w, h3, l3);
            uint2 hv = make_uint2((uint32_t)h0 | ((uint32_t)h1 << 16),
                                  (uint32_t)h2 | ((uint32_t)h3 << 16));
            uint2 lv = make_uint2((uint32_t)l0 | ((uint32_t)l1 << 16),
                                  (uint32_t)l2 | ((uint32_t)l3 << 16));
            uint32_t sw = SW128((uint32_t)((d >> 3) * 1024 + (d & 7) * 128 + y4 * 2));
            *(uint2*)(p + (KHI - base) + sw) = hv;
            *(uint2*)(p + (KLO - base) + sw) = lv;
        }
        FENCE_PROXY_ASYNC_SHARED_CTA();
        __syncthreads();

        // ---- MMA1: S = Q^T K ----
        if (wid == 0 && elect_one_pred()) {
            uint64_t ah = desc_k_major(QHI), al = desc_k_major(QLO);
            uint64_t bh = desc_k_major(KTHI), bl = desc_k_major(KTLO);
#pragma unroll
            for (int s = 0; s < 4; s++) {
                uint64_t so = (uint64_t)(s * 2);
                mma_f16_ss(tmem, ah + so, bh + so, IDESC_BF16_N64, s > 0 ? 1u : 0u);
                mma_f16_ss(tmem, ah + so, bl + so, IDESC_BF16_N64, 1u);
                mma_f16_ss(tmem, al + so, bh + so, IDESC_BF16_N64, 1u);
            }
            TCGEN05_COMMIT(mbar);
        }
        MBARRIER_WAIT_PARITY(mbar, ph & 1); ph++;
        TCGEN05_FENCE_AFTER();

        // ---- LDTM S in x16 halves; mask from global; relu+cnt; stage S' ----
        {
            const int x = sub * 32 + lid;
            const int* mrow = Mb + (size_t)x * L_ + yt * 64 + half * 32;
#pragma unroll
            for (int h16 = 0; h16 < 2; h16++) {
                uint32_t s0[16];
                TCGEN05_LD_32X32B_X16(s0, tmem + half * 32 + h16 * 16);
                TCGEN05_WAIT_LD();
                TCGEN05_FENCE_BEFORE();
                int4 m0 = *(const int4*)(mrow + h16 * 16 + 0);
                int4 m1 = *(const int4*)(mrow + h16 * 16 + 4);
                int4 m2 = *(const int4*)(mrow + h16 * 16 + 8);
                int4 m3 = *(const int4*)(mrow + h16 * 16 + 12);
                int mv[16] = {m0.x, m0.y, m0.z, m0.w, m1.x, m1.y, m1.z, m1.w,
                              m2.x, m2.y, m2.z, m2.w, m3.x, m3.y, m3.z, m3.w};
                uint16_t hh[16], ll[16];
#pragma unroll
                for (int j = 0; j < 16; j++) {
                    float v = __uint_as_float(s0[j]);
                    v = v > 0.f ? v : 0.f;
                    v = mv[j] ? v : 0.f;
                    cnt += mv[j] ? 1 : 0;
                    bf16_split(v, hh[j], ll[j]);
                }
                uint32_t off = (uint32_t)((x >> 3) * 1024 + (x & 7) * 128
                                          + half * 64 + h16 * 32);
#pragma unroll
                for (int g = 0; g < 2; g++) {
                    uint4 hv = make_uint4(
                        (uint32_t)hh[g*8+0] | ((uint32_t)hh[g*8+1] << 16),
                        (uint32_t)hh[g*8+2] | ((uint32_t)hh[g*8+3] << 16),
                        (uint32_t)hh[g*8+4] | ((uint32_t)hh[g*8+5] << 16),
                        (uint32_t)hh[g*8+6] | ((uint32_t)hh[g*8+7] << 16));
                    uint4 lv = make_uint4(
                        (uint32_t)ll[g*8+0] | ((uint32_t)ll[g*8+1] << 16),
                        (uint32_t)ll[g*8+2] | ((uint32_t)ll[g*8+3] << 16),
                        (uint32_t)ll[g*8+4] | ((uint32_t)ll[g*8+5] << 16),
                        (uint32_t)ll[g*8+6] | ((uint32_t)ll[g*8+7] << 16));
                    uint32_t sw = SW128(off + g * 16);
                    *(uint4*)(p + (SHI - base) + sw) = hv;
                    *(uint4*)(p + (SLO - base) + sw) = lv;
                }
            }
        }
        FENCE_PROXY_ASYNC_SHARED_CTA();
        __syncthreads();

        // ---- MMA2: C^T[x,d] += S' K ----
        if (wid == 0 && elect_one_pred()) {
            uint64_t ah = desc_k_major(SHI), al = desc_k_major(SLO);
            uint64_t bh = desc_k_major(KHI), bl = desc_k_major(KLO);
#pragma unroll
            for (int s = 0; s < 4; s++) {
                uint64_t so = (uint64_t)(s * 2);
                mma_f16_ss(tmem + 64, ah + so, bh + so, IDESC_BF16_N64,
                           (yt == 0 && s == 0) ? 0u : 1u);
                mma_f16_ss(tmem + 64, ah + so, bl + so, IDESC_BF16_N64, 1u);
                mma_f16_ss(tmem + 64, al + so, bh + so, IDESC_BF16_N64, 1u);
            }
            TCGEN05_COMMIT(mbar);
        }
        if (yt + 1 < 16) load_k_regs((yt + 1) * 64);   // overlaps MMA2
        MBARRIER_WAIT_PARITY(mbar, ph & 1); ph++;
    }

    TCGEN05_FENCE_AFTER();

    // ---- epilogue: combine counts, normalize, transpose via d-major scr ----
    {
        const int x = sub * 32 + lid;
        float* scr = (float*)p;
        __syncthreads();
        cnts[half * 128 + x] = cnt;
        __syncthreads();
        int tot = cnts[x] + cnts[128 + x];
        float inv = 1.0f / (float)(tot > 0 ? tot : 1);
#pragma unroll
        for (int h16 = 0; h16 < 2; h16++) {
            uint32_t c0[16];
            TCGEN05_LD_32X32B_X16(c0, tmem + 64 + half * 32 + h16 * 16);
            TCGEN05_WAIT_LD();
            TCGEN05_FENCE_BEFORE();
#pragma unroll
            for (int j = 0; j < 16; j++) {
                float v = __uint_as_float(c0[j]) * inv;
                scr[(half * 32 + h16 * 16 + j) * 132 + x] = v;
            }
        }
        __syncthreads();
        float* Cb = C + ((size_t)(b * U_ + h * D_)) * L_ + x0;
#pragma unroll 2
        for (int t = 0; t < 8; t++) {
            int idx = tid + t * 256;
            int d  = idx >> 5;
            int x4 = (idx & 31) << 2;
            float4 v = *(float4*)&scr[d * 132 + x4];
            *(float4*)(Cb + (size_t)d * L_ + x4) = v;
        }
    }
    __syncthreads();
    if (wid == 0) TCGEN05_DEALLOC(tmem, 256);
#else
    (void)Q; (void)K; (void)mask; (void)C;
#endif
}

// ---------------------------------------------------------------------------
extern "C" void kernel_launch(void* const* d_in, const int* in_sizes, int n_in,
                              void* d_out, int out_size)
{
    const float* x  = (const float*)d_in[0];
    const float* y  = (const float*)d_in[1];
    const int*   mk = (const int*)d_in[2];
    const float* wq = (const float*)d_in[3];
    const float* wk = (const float*)d_in[4];
    const float* wo = (const float*)d_in[5];
    float* out = (float*)d_out;

    float *Qp, *Kp, *Cp;
    cudaGetSymbolAddress((void**)&Qp, g_Q);
    cudaGetSymbolAddress((void**)&Kp, g_K);
    cudaGetSymbolAddress((void**)&Cp, g_C);

    cudaFuncSetAttribute(tc_gemm<false>, cudaFuncAttributeMaxDynamicSharedMemorySize,
                         TCG_SMEM_BYTES);
    cudaFuncSetAttribute(tc_gemm<true>, cudaFuncAttributeMaxDynamicSharedMemorySize,
                         TCG_SMEM_BYTES);
    cudaFuncSetAttribute(attn_tc, cudaFuncAttributeMaxDynamicSharedMemorySize,
                         AT_SMEM_BYTES);

    // fused Q+K projection: z in [0,16) -> Q=wq*x, z in [16,32) -> K=wk*y
    tc_gemm<false><<<dim3(L_ / 128, U_ / 128, 2 * B_), 256, TCG_SMEM_BYTES>>>(
        wq, x, wk, y, nullptr, Qp, Kp);
    attn_tc<<<dim3(H_, L_ / 128, B_), 256, AT_SMEM_BYTES>>>(Qp, Kp, mk, Cp);
    tc_gemm<true><<<dim3(L_ / 128, U_ / 128, B_), 256, TCG_SMEM_BYTES>>>(
        wo, Qp, nullptr, nullptr, Cp, out, nullptr);
}

// round 13
// speedup vs baseline: 3.2237x; 1.0086x over previous
#include <cuda_runtime.h>
#include <cuda_bf16.h>
#include <cstdint>
#include <cstddef>

// Problem constants
#define B_  16
#define U_  512
#define L_  1024
#define H_  8
#define D_  64
#define SCALE_ 0.125f   // 1/sqrt(64)

// Scratch (device globals — allocation-free rule).
__device__ __align__(256) float g_Q[(size_t)B_ * U_ * L_];
__device__ __align__(256) float g_K[(size_t)B_ * U_ * L_];
__device__ __align__(256) float g_C[(size_t)B_ * U_ * L_];

// ===========================================================================
// Arch gating
// ===========================================================================
#if defined(__CUDA_ARCH_FEAT_SM103_ALL) || defined(__CUDA_ARCH_FEAT_SM100_ALL) || \
    defined(__CUDA_ARCH_FAMILY_SPECIFIC__) || defined(__CUDA_ARCH_SPECIFIC__)
#define TC_OK 1
#else
#define TC_OK 0
#endif

__device__ __forceinline__ uint32_t smem_to_u32(const void* p) {
    uint32_t a;
    asm("{ .reg .u64 t; cvta.to.shared.u64 t, %1; cvt.u32.u64 %0, t; }" : "=r"(a) : "l"(p));
    return a;
}
#define MBARRIER_INIT(mbar, count) \
    asm volatile("mbarrier.init.shared.b64 [%0], %1;" \
                 :: "r"((uint32_t)(mbar)), "r"((uint32_t)(count)) : "memory")
#define MBARRIER_WAIT_PARITY(mbar, parity) do {                                   \
    uint32_t _m = (uint32_t)(mbar); uint32_t _p = (uint32_t)(parity);             \
    asm volatile("{\n\t.reg .pred P1;\n\t"                                        \
        "WAIT_LOOP_%=:\n\t"                                                        \
        "mbarrier.try_wait.parity.acquire.cta.shared::cta.b64 P1, [%0], %1, 0x989680;\n\t" \
        "@P1 bra.uni WAIT_DONE_%=;\n\t"                                            \
        "bra.uni WAIT_LOOP_%=;\n\t"                                                \
        "WAIT_DONE_%=:\n\t}" :: "r"(_m), "r"(_p) : "memory");                      \
} while (0)
#define FENCE_PROXY_ASYNC_SHARED_CTA() asm volatile("fence.proxy.async.shared::cta;" ::: "memory")

#if TC_OK
__device__ __forceinline__ uint32_t elect_one_pred() {
    uint32_t pred;
    asm volatile("{\n\t.reg .pred p;\n\telect.sync _|p, 0xFFFFFFFF;\n\tselp.b32 %0, 1, 0, p;\n\t}"
                 : "=r"(pred));
    return pred;
}
#define TCGEN05_ALLOC(smem_result_addr, nCols) \
    asm volatile("tcgen05.alloc.cta_group::1.sync.aligned.shared::cta.b32 [%0], %1;" \
                 :: "r"((uint32_t)(smem_result_addr)), "r"((uint32_t)(nCols)) : "memory")
#define TCGEN05_DEALLOC(tmem_addr, nCols) \
    asm volatile("tcgen05.dealloc.cta_group::1.sync.aligned.b32 %0, %1;" \
                 :: "r"(tmem_addr), "r"((uint32_t)(nCols)))
#define TCGEN05_RELINQUISH() \
    asm volatile("tcgen05.relinquish_alloc_permit.cta_group::1.sync.aligned;")
#define TCGEN05_COMMIT(mbar) \
    asm volatile("tcgen05.commit.cta_group::1.mbarrier::arrive::one.shared::cluster.b64 [%0];" \
                 :: "r"((uint32_t)(mbar)) : "memory")
#define TCGEN05_FENCE_BEFORE() asm volatile("tcgen05.fence::before_thread_sync;" ::: "memory")
#define TCGEN05_FENCE_AFTER()  asm volatile("tcgen05.fence::after_thread_sync;"  ::: "memory")
#define TCGEN05_WAIT_LD()      asm volatile("tcgen05.wait::ld.sync.aligned;"     ::: "memory")
#define TCGEN05_LD_32X32B_X32(r, tmem_addr) \
    asm volatile( \
        "tcgen05.ld.sync.aligned.32x32b.x32.b32 " \
        "{%0, %1, %2, %3, %4, %5, %6, %7, " \
        " %8, %9, %10, %11, %12, %13, %14, %15, " \
        " %16, %17, %18, %19, %20, %21, %22, %23, " \
        " %24, %25, %26, %27, %28, %29, %30, %31}, [%32];" \
        : "=r"((r)[0]),  "=r"((r)[1]),  "=r"((r)[2]),  "=r"((r)[3]), \
          "=r"((r)[4]),  "=r"((r)[5]),  "=r"((r)[6]),  "=r"((r)[7]), \
          "=r"((r)[8]),  "=r"((r)[9]),  "=r"((r)[10]), "=r"((r)[11]), \
          "=r"((r)[12]), "=r"((r)[13]), "=r"((r)[14]), "=r"((r)[15]), \
          "=r"((r)[16]), "=r"((r)[17]), "=r"((r)[18]), "=r"((r)[19]), \
          "=r"((r)[20]), "=r"((r)[21]), "=r"((r)[22]), "=r"((r)[23]), \
          "=r"((r)[24]), "=r"((r)[25]), "=r"((r)[26]), "=r"((r)[27]), \
          "=r"((r)[28]), "=r"((r)[29]), "=r"((r)[30]), "=r"((r)[31]) \
        : "r"(tmem_addr))
#define TCGEN05_LD_32X32B_X16(r, tmem_addr) \
    asm volatile( \
        "tcgen05.ld.sync.aligned.32x32b.x16.b32 " \
        "{%0, %1, %2, %3, %4, %5, %6, %7, " \
        " %8, %9, %10, %11, %12, %13, %14, %15}, [%16];" \
        : "=r"((r)[0]),  "=r"((r)[1]),  "=r"((r)[2]),  "=r"((r)[3]), \
          "=r"((r)[4]),  "=r"((r)[5]),  "=r"((r)[6]),  "=r"((r)[7]), \
          "=r"((r)[8]),  "=r"((r)[9]),  "=r"((r)[10]), "=r"((r)[11]), \
          "=r"((r)[12]), "=r"((r)[13]), "=r"((r)[14]), "=r"((r)[15]) \
        : "r"(tmem_addr))

__device__ __forceinline__ void mma_f16_ss(uint32_t d_tmem, uint64_t a_desc,
                                           uint64_t b_desc, uint32_t idesc,
                                           uint32_t enable) {
    asm volatile(
        "{\n\t"
        ".reg .pred p;\n\t"
        "setp.ne.u32 p, %5, 0;\n\t"
        "tcgen05.mma.cta_group::1.kind::f16 [%0], %1, %2, %3, {%4, %4, %4, %4}, p;\n\t"
        "}"
        :: "r"(d_tmem), "l"(a_desc), "l"(b_desc), "r"(idesc), "r"(0u), "r"(enable)
        : "memory");
}
#endif  // TC_OK

// K-major SW128 descriptor
__device__ __forceinline__ uint64_t desc_k_major(uint32_t addr) {
    return ((uint64_t)(addr >> 4) & 0x3FFF)
         | (1ull << 16) | (64ull << 32) | (1ull << 46) | (2ull << 61);
}

#define SW128(off) ((off) ^ (((off) >> 3) & 0x70))

#define IDESC_BF16_N128 0x8200490u
#define IDESC_BF16_N64  0x8100490u

__device__ __forceinline__ void bf16_split(float x, uint16_t& hi, uint16_t& lo) {
    __nv_bfloat16 h = __float2bfloat16(x);
    float r = x - __bfloat162float(h);
    __nv_bfloat16 l = __float2bfloat16(r);
    hi = __bfloat16_as_ushort(h);
    lo = __bfloat16_as_ushort(l);
}

// ===========================================================================
// tcgen05 split-bf16 channel-mix GEMM (R12 proven, unchanged).
// ===========================================================================
#define TCG_SMEM_BYTES 66688

template <bool FUSE>
__global__ __launch_bounds__(256, 2) __cluster_dims__(1, 1, 1) void tc_gemm(
    const float* __restrict__ Wa, const float* __restrict__ Xa,
    const float* __restrict__ Wb, const float* __restrict__ Xb,
    const float* __restrict__ X2, float* __restrict__ OutA,
    float* __restrict__ OutB)
{
#if TC_OK
    extern __shared__ uint8_t dsm[];
    const uint32_t raw  = smem_to_u32(dsm);
    const uint32_t base = (raw + 1023u) & ~1023u;
    uint8_t* p = dsm + (base - raw);

    const uint32_t ctrl = base + 65536;
    const uint32_t mbar = ctrl + 8;

    const float* W; const float* X1; float* Out; int b;
    if (blockIdx.z < B_) { W = Wa; X1 = Xa; Out = OutA; b = blockIdx.z; }
    else                 { W = Wb; X1 = Xb; Out = OutB; b = blockIdx.z - B_; }

    const int row0 = blockIdx.y * 128;
    const int col0 = blockIdx.x * 128;
    const int tid  = threadIdx.x;
    const int wid  = tid >> 5;
    const int lid  = tid & 31;

    if (wid == 0) {
        TCGEN05_ALLOC(ctrl, 256);
        TCGEN05_RELINQUISH();
    }
    if (tid == 0) MBARRIER_INIT(mbar, 1);
    __syncthreads();
    uint32_t tmem;
    asm volatile("ld.shared.b32 %0, [%1];" : "=r"(tmem) : "r"(ctrl));

    const float* Wb_  = W + (size_t)row0 * U_;
    const float* X1b = X1 + (size_t)b * U_ * L_ + col0;
    const float* X2b = FUSE ? (X2 + (size_t)b * U_ * L_ + col0) : nullptr;

    float4 aR[8];
    float  bR[4][8];

    auto load_regs = [&](int c) {
        const int k0 = c * 64;
#pragma unroll
        for (int t = 0; t < 8; t++) {
            int idx = tid + t * 256;
            int m  = idx >> 4;
            int k4 = (idx & 15) << 2;
            aR[t] = *(const float4*)(Wb_ + (size_t)m * U_ + k0 + k4);
        }
#pragma unroll
        for (int ei = 0; ei < 4; ei++) {
            int n = lid + 32 * ei;
#pragma unroll
            for (int kk = 0; kk < 8; kk++) {
                size_t ro = (size_t)(k0 + wid * 8 + kk) * L_ + n;
                float v = X1b[ro];
                if (FUSE) v = 0.5f * (v + X2b[ro]);
                bR[ei][kk] = v;
            }
        }
    };

    auto store_stage = [&]() {
#pragma unroll
        for (int t = 0; t < 8; t++) {
            int idx = tid + t * 256;
            int m  = idx >> 4;
            int k4 = (idx & 15) << 2;
            float4 v = aR[t];
            uint16_t h0, l0, h1, l1, h2, l2, h3, l3;
            bf16_split(v.x, h0, l0); bf16_split(v.y, h1, l1);
            bf16_split(v.z, h2, l2); bf16_split(v.w, h3, l3);
            uint2 hv = make_uint2((uint32_t)h0 | ((uint32_t)h1 << 16),
                                  (uint32_t)h2 | ((uint32_t)h3 << 16));
            uint2 lv = make_uint2((uint32_t)l0 | ((uint32_t)l1 << 16),
                                  (uint32_t)l2 | ((uint32_t)l3 << 16));
            uint32_t off = (uint32_t)((m >> 3) * 1024 + (m & 7) * 128 + k4 * 2);
            uint32_t sw = SW128(off);
            *(uint2*)(p + sw)         = hv;
            *(uint2*)(p + 16384 + sw) = lv;
        }
#pragma unroll
        for (int ei = 0; ei < 4; ei++) {
            int n = lid + 32 * ei;
            uint16_t h[8], l[8];
#pragma unroll
            for (int kk = 0; kk < 8; kk++) bf16_split(bR[ei][kk], h[kk], l[kk]);
            uint4 hv = make_uint4((uint32_t)h[0] | ((uint32_t)h[1] << 16),
                                  (uint32_t)h[2] | ((uint32_t)h[3] << 16),
                                  (uint32_t)h[4] | ((uint32_t)h[5] << 16),
                                  (uint32_t)h[6] | ((uint32_t)h[7] << 16));
            uint4 lv = make_uint4((uint32_t)l[0] | ((uint32_t)l[1] << 16),
                                  (uint32_t)l[2] | ((uint32_t)l[3] << 16),
                                  (uint32_t)l[4] | ((uint32_t)l[5] << 16),
                                  (uint32_t)l[6] | ((uint32_t)l[7] << 16));
            uint32_t off = (uint32_t)((n >> 3) * 1024 + (n & 7) * 128 + wid * 16);
            uint32_t sw = SW128(off);
            *(uint4*)(p + 32768 + sw) = hv;
            *(uint4*)(p + 49152 + sw) = lv;
        }
        FENCE_PROXY_ASYNC_SHARED_CTA();
    };

    load_regs(0);
    store_stage();
    __syncthreads();

    const int NC = U_ / 64;   // 8 chunks
    for (int c = 0; c < NC; c++) {
        if (wid == 0 && elect_one_pred()) {
            uint64_t ahi = desc_k_major(base);
            uint64_t alo = desc_k_major(base + 16384);
            uint64_t bhi = desc_k_major(base + 32768);
            uint64_t blo = desc_k_major(base + 49152);
#pragma unroll
            for (int s = 0; s < 4; s++) {
                uint64_t so = (uint64_t)(s * 2);
                mma_f16_ss(tmem, ahi + so, bhi + so, IDESC_BF16_N128,
                           (c == 0 && s == 0) ? 0u : 1u);
                mma_f16_ss(tmem, ahi + so, blo + so, IDESC_BF16_N128, 1u);
                mma_f16_ss(tmem, alo + so, bhi + so, IDESC_BF16_N128, 1u);
            }
            TCGEN05_COMMIT(mbar);
        }
        if (c + 1 < NC) load_regs(c + 1);
        MBARRIER_WAIT_PARITY(mbar, c & 1);
        if (c + 1 < NC) {
            store_stage();
            __syncthreads();
        }
    }

    TCGEN05_FENCE_AFTER();

    if (wid < 4) {
        const int m = wid * 32 + lid;
        float* op = Out + ((size_t)b * U_ + row0 + m) * L_ + col0;
#pragma unroll
        for (int j = 0; j < 4; j++) {
            uint32_t r32[32];
            TCGEN05_LD_32X32B_X32(r32, tmem + j * 32);
            TCGEN05_WAIT_LD();
            TCGEN05_FENCE_BEFORE();
#pragma unroll
            for (int q = 0; q < 8; q++) {
                float4 v = make_float4(__uint_as_float(r32[q * 4 + 0]),
                                       __uint_as_float(r32[q * 4 + 1]),
                                       __uint_as_float(r32[q * 4 + 2]),
                                       __uint_as_float(r32[q * 4 + 3]));
                *(float4*)(op + j * 32 + q * 4) = v;
            }
        }
    }
    __syncthreads();
    if (wid == 0) TCGEN05_DEALLOC(tmem, 256);
#else
    (void)Wa; (void)Xa; (void)Wb; (void)Xb; (void)X2; (void)OutA; (void)OutB;
#endif
}

// ===========================================================================
// tcgen05 attention — single-sync pipelined loop (MMA2(yt)+MMA1(yt+1) issued
// together; LDTM/convert overlaps MMA2(yt-1); prefetch overlaps both MMAs).
// smem: QHI 0 | QLO 16384 | KTHI 32768 | KTLO 40960 | KHI 49152 | KLO 57344
//       SHI 65536 | SLO 81920 | ctrl 98304 | cnts 98336
// ===========================================================================
#define AT_SMEM_BYTES 100384

__global__ __launch_bounds__(256, 2) __cluster_dims__(1, 1, 1) void attn_tc(
    const float* __restrict__ Q, const float* __restrict__ K,
    const int* __restrict__ mask, float* __restrict__ C)
{
#if TC_OK
    extern __shared__ uint8_t dsm[];
    const uint32_t raw  = smem_to_u32(dsm);
    const uint32_t base = (raw + 1023u) & ~1023u;
    uint8_t* p = dsm + (base - raw);

    const uint32_t QHI = base, QLO = base + 16384;
    const uint32_t KTHI = base + 32768, KTLO = base + 40960;
    const uint32_t KHI = base + 49152, KLO = base + 57344;
    const uint32_t SHI = base + 65536, SLO = base + 81920;
    const uint32_t ctrl = base + 98304;
    const uint32_t m1 = ctrl + 8;
    const uint32_t m2 = ctrl + 16;
    int* cnts = (int*)(p + 98336);

    const int b  = blockIdx.z;
    const int h  = blockIdx.x;
    const int x0 = blockIdx.y * 128;
    const int tid = threadIdx.x;
    const int wid = tid >> 5;
    const int lid = tid & 31;
    const int sub  = wid & 3;
    const int half = wid >> 2;

    if (wid == 0) {
        TCGEN05_ALLOC(ctrl, 256);
        TCGEN05_RELINQUISH();
    }
    if (tid == 0) { MBARRIER_INIT(m1, 1); MBARRIER_INIT(m2, 1); }
    __syncthreads();
    uint32_t tmem;
    asm volatile("ld.shared.b32 %0, [%1];" : "=r"(tmem) : "r"(ctrl));

    const float* Qb = Q + ((size_t)(b * U_ + h * D_)) * L_ + x0;
    const float* Kb = K + ((size_t)(b * U_ + h * D_)) * L_;
    const int*   Mb = mask + ((size_t)b * L_ + x0) * L_;

    // ---- stage Q^T [128x][64d] hi/lo (scale folded), once ----
#pragma unroll
    for (int ei = 0; ei < 4; ei++) {
        int x = lid + 32 * ei;
        float rv[8];
#pragma unroll
        for (int kk = 0; kk < 8; kk++)
            rv[kk] = Qb[(size_t)(wid * 8 + kk) * L_ + x] * SCALE_;
        uint16_t hh[8], ll[8];
#pragma unroll
        for (int kk = 0; kk < 8; kk++) bf16_split(rv[kk], hh[kk], ll[kk]);
        uint4 hv = make_uint4((uint32_t)hh[0] | ((uint32_t)hh[1] << 16),
                              (uint32_t)hh[2] | ((uint32_t)hh[3] << 16),
                              (uint32_t)hh[4] | ((uint32_t)hh[5] << 16),
                              (uint32_t)hh[6] | ((uint32_t)hh[7] << 16));
        uint4 lv = make_uint4((uint32_t)ll[0] | ((uint32_t)ll[1] << 16),
                              (uint32_t)ll[2] | ((uint32_t)ll[3] << 16),
                              (uint32_t)ll[4] | ((uint32_t)ll[5] << 16),
                              (uint32_t)ll[6] | ((uint32_t)ll[7] << 16));
        uint32_t sw = SW128((uint32_t)((x >> 3) * 1024 + (x & 7) * 128 + wid * 16));
        *(uint4*)(p + (QHI - base) + sw) = hv;
        *(uint4*)(p + (QLO - base) + sw) = lv;
    }

    // reg prefetch state: ktR holds KT(next), kR holds K(current)
    float  ktR[2][8];
    float4 kR[4];

    auto load_kt_regs = [&](int y0n) {
#pragma unroll
        for (int ei = 0; ei < 2; ei++) {
            int y = lid + 32 * ei;
#pragma unroll
            for (int kk = 0; kk < 8; kk++)
                ktR[ei][kk] = Kb[(size_t)(wid * 8 + kk) * L_ + y0n + y];
        }
    };
    auto load_k_regs = [&](int y0n) {
#pragma unroll
        for (int t = 0; t < 4; t++) {
            int idx = tid + t * 256;
            int d  = idx >> 4;
            int y4 = (idx & 15) << 2;
            kR[t] = *(const float4*)(Kb + (size_t)d * L_ + y0n + y4);
        }
    };
    auto store_kt = [&]() {
#pragma unroll
        for (int ei = 0; ei < 2; ei++) {
            int y = lid + 32 * ei;
            uint16_t hh[8], ll[8];
#pragma unroll
            for (int kk = 0; kk < 8; kk++) bf16_split(ktR[ei][kk], hh[kk], ll[kk]);
            uint4 hv = make_uint4((uint32_t)hh[0] | ((uint32_t)hh[1] << 16),
                                  (uint32_t)hh[2] | ((uint32_t)hh[3] << 16),
                                  (uint32_t)hh[4] | ((uint32_t)hh[5] << 16),
                                  (uint32_t)hh[6] | ((uint32_t)hh[7] << 16));
            uint4 lv = make_uint4((uint32_t)ll[0] | ((uint32_t)ll[1] << 16),
                                  (uint32_t)ll[2] | ((uint32_t)ll[3] << 16),
                                  (uint32_t)ll[4] | ((uint32_t)ll[5] << 16),
                                  (uint32_t)ll[6] | ((uint32_t)ll[7] << 16));
            uint32_t sw = SW128((uint32_t)((y >> 3) * 1024 + (y & 7) * 128 + wid * 16));
            *(uint4*)(p + (KTHI - base) + sw) = hv;
            *(uint4*)(p + (KTLO - base) + sw) = lv;
        }
    };
    auto store_k = [&]() {
#pragma unroll
        for (int t = 0; t < 4; t++) {
            int idx = tid + t * 256;
            int d  = idx >> 4;
            int y4 = (idx & 15) << 2;
            float4 v = kR[t];
            uint16_t h0, l0, h1, l1, h2, l2, h3, l3;
            bf16_split(v.x, h0, l0); bf16_split(v.y, h1, l1);
            bf16_split(v.z, h2, l2); bf16_split(v.w, h3, l3);
            uint2 hv = make_uint2((uint32_t)h0 | ((uint32_t)h1 << 16),
                                  (uint32_t)h2 | ((uint32_t)h3 << 16));
            uint2 lv = make_uint2((uint32_t)l0 | ((uint32_t)l1 << 16),
                                  (uint32_t)l2 | ((uint32_t)l3 << 16));
            uint32_t sw = SW128((uint32_t)((d >> 3) * 1024 + (d & 7) * 128 + y4 * 2));
            *(uint2*)(p + (KHI - base) + sw) = hv;
            *(uint2*)(p + (KLO - base) + sw) = lv;
        }
    };

    // prologue: stage KT(0), issue MMA1(0); prefetch KT(1), K(0)
    load_kt_regs(0);
    store_kt();
    FENCE_PROXY_ASYNC_SHARED_CTA();
    __syncthreads();
    if (wid == 0 && elect_one_pred()) {
        uint64_t ah = desc_k_major(QHI), al = desc_k_major(QLO);
        uint64_t bh = desc_k_major(KTHI), bl = desc_k_major(KTLO);
#pragma unroll
        for (int s = 0; s < 4; s++) {
            uint64_t so = (uint64_t)(s * 2);
            mma_f16_ss(tmem, ah + so, bh + so, IDESC_BF16_N64, s > 0 ? 1u : 0u);
            mma_f16_ss(tmem, ah + so, bl + so, IDESC_BF16_N64, 1u);
            mma_f16_ss(tmem, al + so, bh + so, IDESC_BF16_N64, 1u);
        }
        TCGEN05_COMMIT(m1);
    }
    load_kt_regs(64);
    load_k_regs(0);

    int cnt = 0;
    const int x = sub * 32 + lid;

    for (int yt = 0; yt < 16; yt++) {
        // ---- wait MMA1(yt); LDTM S + relu/mask/cnt (overlaps MMA2(yt-1)) ----
        MBARRIER_WAIT_PARITY(m1, yt & 1);
        TCGEN05_FENCE_AFTER();

        uint4 sh[2][2], sl[2][2];   // packed S' hi/lo, both x16 halves
        const int* mrow = Mb + (size_t)x * L_ + yt * 64 + half * 32;
#pragma unroll
        for (int h16 = 0; h16 < 2; h16++) {
            uint32_t s0[16];
            TCGEN05_LD_32X32B_X16(s0, tmem + half * 32 + h16 * 16);
            TCGEN05_WAIT_LD();
            TCGEN05_FENCE_BEFORE();
            int4 m0 = *(const int4*)(mrow + h16 * 16 + 0);
            int4 m1v = *(const int4*)(mrow + h16 * 16 + 4);
            int4 m2v = *(const int4*)(mrow + h16 * 16 + 8);
            int4 m3 = *(const int4*)(mrow + h16 * 16 + 12);
            int mv[16] = {m0.x, m0.y, m0.z, m0.w, m1v.x, m1v.y, m1v.z, m1v.w,
                          m2v.x, m2v.y, m2v.z, m2v.w, m3.x, m3.y, m3.z, m3.w};
            uint16_t hh[16], ll[16];
#pragma unroll
            for (int j = 0; j < 16; j++) {
                float v = __uint_as_float(s0[j]);
                v = v > 0.f ? v : 0.f;
                v = mv[j] ? v : 0.f;
                cnt += mv[j] ? 1 : 0;
                bf16_split(v, hh[j], ll[j]);
            }
#pragma unroll
            for (int g = 0; g < 2; g++) {
                sh[h16][g] = make_uint4(
                    (uint32_t)hh[g*8+0] | ((uint32_t)hh[g*8+1] << 16),
                    (uint32_t)hh[g*8+2] | ((uint32_t)hh[g*8+3] << 16),
                    (uint32_t)hh[g*8+4] | ((uint32_t)hh[g*8+5] << 16),
                    (uint32_t)hh[g*8+6] | ((uint32_t)hh[g*8+7] << 16));
                sl[h16][g] = make_uint4(
                    (uint32_t)ll[g*8+0] | ((uint32_t)ll[g*8+1] << 16),
                    (uint32_t)ll[g*8+2] | ((uint32_t)ll[g*8+3] << 16),
                    (uint32_t)ll[g*8+4] | ((uint32_t)ll[g*8+5] << 16),
                    (uint32_t)ll[g*8+6] | ((uint32_t)ll[g*8+7] << 16));
            }
        }

        // ---- wait MMA2(yt-1): frees S and K buffers ----
        if (yt > 0) MBARRIER_WAIT_PARITY(m2, (yt - 1) & 1);

        // ---- store S'(yt), K(yt), KT(yt+1) ----
        {
            uint32_t off = (uint32_t)((x >> 3) * 1024 + (x & 7) * 128 + half * 64);
#pragma unroll
            for (int h16 = 0; h16 < 2; h16++)
#pragma unroll
                for (int g = 0; g < 2; g++) {
                    uint32_t sw = SW128(off + h16 * 32 + g * 16);
                    *(uint4*)(p + (SHI - base) + sw) = sh[h16][g];
                    *(uint4*)(p + (SLO - base) + sw) = sl[h16][g];
                }
        }
        store_k();
        if (yt + 1 < 16) store_kt();
        FENCE_PROXY_ASYNC_SHARED_CTA();
        __syncthreads();

        // ---- issue MMA2(yt) and MMA1(yt+1) back-to-back ----
        if (wid == 0 && elect_one_pred()) {
            {
                uint64_t ah = desc_k_major(SHI), al = desc_k_major(SLO);
                uint64_t bh = desc_k_major(KHI), bl = desc_k_major(KLO);
#pragma unroll
                for (int s = 0; s < 4; s++) {
                    uint64_t so = (uint64_t)(s * 2);
                    mma_f16_ss(tmem + 64, ah + so, bh + so, IDESC_BF16_N64,
                               (yt == 0 && s == 0) ? 0u : 1u);
                    mma_f16_ss(tmem + 64, ah + so, bl + so, IDESC_BF16_N64, 1u);
                    mma_f16_ss(tmem + 64, al + so, bh + so, IDESC_BF16_N64, 1u);
                }
                TCGEN05_COMMIT(m2);
            }
            if (yt + 1 < 16) {
                uint64_t ah = desc_k_major(QHI), al = desc_k_major(QLO);
                uint64_t bh = desc_k_major(KTHI), bl = desc_k_major(KTLO);
#pragma unroll
                for (int s = 0; s < 4; s++) {
                    uint64_t so = (uint64_t)(s * 2);
                    mma_f16_ss(tmem, ah + so, bh + so, IDESC_BF16_N64,
                               s > 0 ? 1u : 0u);
                    mma_f16_ss(tmem, ah + so, bl + so, IDESC_BF16_N64, 1u);
                    mma_f16_ss(tmem, al + so, bh + so, IDESC_BF16_N64, 1u);
                }
                TCGEN05_COMMIT(m1);
            }
        }

        // ---- prefetch next K/KT regs (overlaps both MMAs) ----
        if (yt + 1 < 16) {
            load_k_regs((yt + 1) * 64);
            if (yt + 2 < 16) load_kt_regs((yt + 2) * 64);
        }
    }

    // final MMA2(15) completion: phase 15 -> parity 1
    MBARRIER_WAIT_PARITY(m2, 1);
    TCGEN05_FENCE_AFTER();

    // ---- epilogue: combine counts, normalize, transpose via d-major scr ----
    {
        float* scr = (float*)p;
        __syncthreads();
        cnts[half * 128 + x] = cnt;
        __syncthreads();
        int tot = cnts[x] + cnts[128 + x];
        float inv = 1.0f / (float)(tot > 0 ? tot : 1);
#pragma unroll
        for (int h16 = 0; h16 < 2; h16++) {
            uint32_t c0[16];
            TCGEN05_LD_32X32B_X16(c0, tmem + 64 + half * 32 + h16 * 16);
            TCGEN05_WAIT_LD();
            TCGEN05_FENCE_BEFORE();
#pragma unroll
            for (int j = 0; j < 16; j++) {
                float v = __uint_as_float(c0[j]) * inv;
                scr[(half * 32 + h16 * 16 + j) * 132 + x] = v;
            }
        }
        __syncthreads();
        float* Cb = C + ((size_t)(b * U_ + h * D_)) * L_ + x0;
#pragma unroll 2
        for (int t = 0; t < 8; t++) {
            int idx = tid + t * 256;
            int d  = idx >> 5;
            int x4 = (idx & 31) << 2;
            float4 v = *(float4*)&scr[d * 132 + x4];
            *(float4*)(Cb + (size_t)d * L_ + x4) = v;
        }
    }
    __syncthreads();
    if (wid == 0) TCGEN05_DEALLOC(tmem, 256);
#else
    (void)Q; (void)K; (void)mask; (void)C;
#endif
}

// ---------------------------------------------------------------------------
extern "C" void kernel_launch(void* const* d_in, const int* in_sizes, int n_in,
                              void* d_out, int out_size)
{
    const float* x  = (const float*)d_in[0];
    const float* y  = (const float*)d_in[1];
    const int*   mk = (const int*)d_in[2];
    const float* wq = (const float*)d_in[3];
    const float* wk = (const float*)d_in[4];
    const float* wo = (const float*)d_in[5];
    float* out = (float*)d_out;

    float *Qp, *Kp, *Cp;
    cudaGetSymbolAddress((void**)&Qp, g_Q);
    cudaGetSymbolAddress((void**)&Kp, g_K);
    cudaGetSymbolAddress((void**)&Cp, g_C);

    cudaFuncSetAttribute(tc_gemm<false>, cudaFuncAttributeMaxDynamicSharedMemorySize,
                         TCG_SMEM_BYTES);
    cudaFuncSetAttribute(tc_gemm<true>, cudaFuncAttributeMaxDynamicSharedMemorySize,
                         TCG_SMEM_BYTES);
    cudaFuncSetAttribute(attn_tc, cudaFuncAttributeMaxDynamicSharedMemorySize,
                         AT_SMEM_BYTES);

    // fused Q+K projection: z in [0,16) -> Q=wq*x, z in [16,32) -> K=wk*y
    tc_gemm<false><<<dim3(L_ / 128, U_ / 128, 2 * B_), 256, TCG_SMEM_BYTES>>>(
        wq, x, wk, y, nullptr, Qp, Kp);
    attn_tc<<<dim3(H_, L_ / 128, B_), 256, AT_SMEM_BYTES>>>(Qp, Kp, mk, Cp);
    tc_gemm<true><<<dim3(L_ / 128, U_ / 128, B_), 256, TCG_SMEM_BYTES>>>(
        wo, Qp, nullptr, nullptr, Cp, out, nullptr);
}